// round 13
// baseline (speedup 1.0000x reference)
#include <cuda_runtime.h>
#include <cuda_fp16.h>
#include <cstdint>

// ---------------- problem constants ----------------
#define N_NODES  100000
#define N_EDGES  400000
#define N_GRAPHS 5000
#define INF_DIM  11
#define H_DIM    256

#define M_PAD    100096   // 1564 * 64
#define G_PAD    5120     // 80 * 64
#define SCAN_NE  (N_NODES + 1)
#define SCAN_NB  ((SCAN_NE + 2047) / 2048)   // 49

// ---------------- scratch (static device globals; no allocation) ----------------
__device__ float  g_a  [(size_t)M_PAD * H_DIM];        // fp32 activations (h)
__device__ float  g_agg11[(size_t)N_NODES * INF_DIM];  // layer-0 aggregation
__device__ __half g_ahi[(size_t)M_PAD * H_DIM];        // (h+agg) hi   (also pooled hi)
__device__ __half g_alo[(size_t)M_PAD * H_DIM];        // (h+agg) lo   (also pooled lo)
__device__ __half g_bhi[(size_t)M_PAD * H_DIM];        // hidden hi
__device__ __half g_blo[(size_t)M_PAD * H_DIM];        // hidden lo
__device__ __half g_wth[10 * 65536];                   // W^T fp16 (10 matrices), [n][k]
__device__ float  g_hid [(size_t)G_PAD * H_DIM];
__device__ int    g_ei[2 * N_EDGES];
__device__ int    g_batch[N_NODES];
__device__ int    g_is32;
// CSR by destination
__device__ int    g_hist[SCAN_NE];
__device__ int    g_rowptr[SCAN_NE];
__device__ int    g_cur[N_NODES];
__device__ int    g_bsum[SCAN_NB];
__device__ int    g_col[N_EDGES];
__device__ int    g_gstart[N_GRAPHS + 1];

// ---------------- async-copy helpers (baseline PTX, sm_80+) ----------------
__device__ __forceinline__ uint32_t smem_to_u32(const void* p) {
    uint32_t a;
    asm("{ .reg .u64 t; cvta.to.shared.u64 t, %1; cvt.u32.u64 %0, t; }" : "=r"(a) : "l"(p));
    return a;
}
#define CP_ASYNC16(dst, src) \
    asm volatile("cp.async.cg.shared.global [%0], [%1], 16;" :: "r"(dst), "l"(src))
#define CP_COMMIT()  asm volatile("cp.async.commit_group;" ::: "memory")
#define CP_WAIT0()   asm volatile("cp.async.wait_group 0;" ::: "memory")
#define CP_WAIT1()   asm volatile("cp.async.wait_group 1;" ::: "memory")

// swizzled byte offset: logical tile rows x 32 fp16 (64B), 2 logical rows per 128B
// physical row; (row r, 16B-chunk c in 0..3) -> conflict-free for ldmatrix & cp.async.
__device__ __forceinline__ uint32_t swoff(int r, int c) {
    int pr = r >> 1;
    int pc = (((r & 1) << 2) | c) ^ (pr & 7);
    return (uint32_t)(pr * 128 + pc * 16);
}

__device__ __forceinline__ void ldsm_x4(uint32_t addr, uint32_t* r) {
    asm volatile("ldmatrix.sync.aligned.m8n8.x4.shared.b16 {%0,%1,%2,%3}, [%4];"
                 : "=r"(r[0]), "=r"(r[1]), "=r"(r[2]), "=r"(r[3]) : "r"(addr));
}
__device__ __forceinline__ void mma16816(float* d, const uint32_t* a, const uint32_t* b) {
    asm volatile("mma.sync.aligned.m16n8k16.row.col.f32.f16.f16.f32 "
                 "{%0,%1,%2,%3}, {%4,%5,%6,%7}, {%8,%9}, {%0,%1,%2,%3};"
                 : "+f"(d[0]), "+f"(d[1]), "+f"(d[2]), "+f"(d[3])
                 : "r"(a[0]), "r"(a[1]), "r"(a[2]), "r"(a[3]), "r"(b[0]), "r"(b[1]));
}

// split fp32 -> fp16 hi/lo
__device__ __forceinline__ void split_h(float v, __half& hi, __half& lo) {
    hi = __float2half_rn(v);
    lo = __float2half_rn(v - __half2float(hi));
}

// ================ split-fp16 tensor-core GEMM (occupancy build: 3 CTAs/SM) ==============
// C[M x 256] = act((Ah + Al)@B^T + bias); A split fp16 (hi/lo), B single fp16; W^T [N][K].
// BM=64, BN=128 (grid.y=2), BK=32, 256 threads = 8 warps (4m x 2n), warp tile 16x64.
// 8 stages over K=256; each stage loads Ahi/Alo (4KB each) + B (8KB) = 16KB.
// Triple-buffered cp.async (48KB smem/CTA), one __syncthreads per stage, 3 CTAs/SM (24 warps).
// mode 0: fp32 + relu. mode 1: fp16 hi/lo split + relu. mode 2: fp32, no relu.
#define STG_BYTES 16384          // Ahi 4K | Alo 4K | B 8K
#define NSTAGE 3
__global__ void __launch_bounds__(256, 3) mmagemm(
    const __half* __restrict__ Ahi, const __half* __restrict__ Alo,
    const __half* __restrict__ B,
    const float* __restrict__ bias,
    float* __restrict__ outF,
    __half* __restrict__ outHi, __half* __restrict__ outLo,
    int mode)
{
    extern __shared__ __align__(128) unsigned char sm[];
    const uint32_t sbase = smem_to_u32(sm);

    const int tid = threadIdx.x, wid = tid >> 5, lane = tid & 31;
    const int m0 = blockIdx.x * 64;
    const int n0 = blockIdx.y * 128;
    const int wm = (wid & 3) * 16, wn = (wid >> 2) * 64;

    // copy slots: A tiles 4KB = 256 chunks (1/thread each); B 8KB = 512 chunks (2/thread)
    const int acr = tid >> 2, acc_c = tid & 3;          // A chunk (rows 0..63)
    const int bcr1 = tid >> 2;                          // B chunk rows 0..63
    const int bcr2 = (tid + 256) >> 2;                  // B chunk rows 64..127
    const uint32_t aslot  = swoff(acr, acc_c);
    const uint32_t bslot1 = swoff(bcr1, acc_c);
    const uint32_t bslot2 = swoff(bcr2, acc_c);

    // ldsm row/chunk params
    const int arow0 = wm + ((lane >> 3) & 1) * 8 + (lane & 7);
    const int ach   = lane >> 4;            // 0..1
    const int brow0 = wn + ((lane >> 4) & 1) * 8 + (lane & 7);
    const int bch   = (lane >> 3) & 1;      // 0..1

    float acc[8][4];
#pragma unroll
    for (int j = 0; j < 8; j++)
#pragma unroll
        for (int k = 0; k < 4; k++) acc[j][k] = 0.f;

    auto issue = [&](int st) {
        const int kk = st << 5;
        const uint32_t sa = sbase + (st % NSTAGE) * STG_BYTES;
        CP_ASYNC16(sa +        aslot,  Ahi + (size_t)(m0 + acr) * H_DIM + kk + acc_c * 8);
        CP_ASYNC16(sa + 4096 + aslot,  Alo + (size_t)(m0 + acr) * H_DIM + kk + acc_c * 8);
        CP_ASYNC16(sa + 8192 + bslot1, B   + (size_t)(n0 + bcr1) * H_DIM + kk + acc_c * 8);
        CP_ASYNC16(sa + 8192 + bslot2, B   + (size_t)(n0 + bcr2) * H_DIM + kk + acc_c * 8);
        CP_COMMIT();
    };

    issue(0); issue(1);
    for (int st = 0; st < 8; st++) {
        if (st < 7) { CP_WAIT1(); } else { CP_WAIT0(); }
        __syncthreads();
        if (st + 2 < 8) issue(st + 2);   // two stages of cp.async slack

        const uint32_t sa = sbase + (st % NSTAGE) * STG_BYTES;
#pragma unroll
        for (int chunk = 0; chunk < 2; chunk++) {
            const int c0 = chunk * 2;
            uint32_t ah[4], al[4], b[8][2];
            ldsm_x4(sa +        swoff(arow0, c0 + ach), ah);
            ldsm_x4(sa + 4096 + swoff(arow0, c0 + ach), al);
#pragma unroll
            for (int p = 0; p < 4; p++) {
                uint32_t r[4];
                ldsm_x4(sa + 8192 + swoff(brow0 + p * 16, c0 + bch), r);
                b[2 * p][0] = r[0]; b[2 * p][1] = r[1];
                b[2 * p + 1][0] = r[2]; b[2 * p + 1][1] = r[3];
            }
            // term 1: Ah*B
#pragma unroll
            for (int nt = 0; nt < 8; nt++) mma16816(acc[nt], ah, b[nt]);
            // term 2: Al*B
#pragma unroll
            for (int nt = 0; nt < 8; nt++) mma16816(acc[nt], al, b[nt]);
        }
    }

    // -------- epilogue --------
#pragma unroll
    for (int nt = 0; nt < 8; nt++) {
        const int ncol = n0 + wn + nt * 8 + (lane & 3) * 2;
        const float b0 = __ldg(&bias[ncol]), b1 = __ldg(&bias[ncol + 1]);
#pragma unroll
        for (int half = 0; half < 2; half++) {
            const int mrow = m0 + wm + (lane >> 2) + half * 8;
            float v0 = acc[nt][2 * half + 0] + b0;
            float v1 = acc[nt][2 * half + 1] + b1;
            if (mode != 2) { v0 = fmaxf(v0, 0.f); v1 = fmaxf(v1, 0.f); }
            if (mode != 1) {
                *(float2*)(outF + (size_t)mrow * H_DIM + ncol) = make_float2(v0, v1);
            } else {
                __half h0, l0v, h1, l1v;
                split_h(v0, h0, l0v);
                split_h(v1, h1, l1v);
                __half2 hh; hh.x = h0; hh.y = h1;
                __half2 ll; ll.x = l0v; ll.y = l1v;
                *(__half2*)(outHi + (size_t)mrow * H_DIM + ncol) = hh;
                *(__half2*)(outLo + (size_t)mrow * H_DIM + ncol) = ll;
            }
        }
    }
}

// ---------------- small utility kernels ----------------
__global__ void zero_f(float* __restrict__ p, int n) {
    int i = blockIdx.x * blockDim.x + threadIdx.x;
    if (i < n) p[i] = 0.f;
}
__global__ void zero_flag() { g_is32 = 0; }

__global__ void detect32(const unsigned int* __restrict__ w) {
    int i = blockIdx.x * blockDim.x + threadIdx.x;
    int idx = 2 * i + 1;
    if (idx < 2 * N_EDGES) { if (w[idx] != 0u) g_is32 = 1; }
}
__global__ void convert_idx(const void* __restrict__ ei_raw, const void* __restrict__ batch_raw) {
    int is32 = g_is32;
    int i = blockIdx.x * blockDim.x + threadIdx.x;
    if (i < 2 * N_EDGES)
        g_ei[i] = is32 ? ((const int*)ei_raw)[i] : (int)((const long long*)ei_raw)[i];
    if (i < N_NODES)
        g_batch[i] = is32 ? ((const int*)batch_raw)[i] : (int)((const long long*)batch_raw)[i];
}

// transpose + convert 10 weight matrices to fp16: wt[mat][n*256+k] = fp16(W[k][n])
__global__ void cvt_w(const float* __restrict__ w0,
                      const float* __restrict__ w1s,
                      const float* __restrict__ w2s,
                      const float* __restrict__ hw1) {
    int b = blockIdx.x;            // 10 * 256 blocks
    int mat = b >> 8, k = b & 255, n = threadIdx.x;
    const float* src = (mat == 0) ? w0
                     : (mat <= 4) ? (w1s + (size_t)(mat - 1) * 65536)
                     : (mat <= 8) ? (w2s + (size_t)(mat - 5) * 65536)
                                  : hw1;
    g_wth[(size_t)mat * 65536 + n * 256 + k] = __float2half_rn(src[k * 256 + n]);
}

// ---------------- CSR build (dst-sorted adjacency) ----------------
__global__ void zero_hist() {
    int i = blockIdx.x * blockDim.x + threadIdx.x;
    if (i < SCAN_NE) g_hist[i] = 0;
}
__global__ void hist_dst() {
    int e = blockIdx.x * blockDim.x + threadIdx.x;
    if (e < N_EDGES) atomicAdd(&g_hist[g_ei[N_EDGES + e] + 1], 1);
}
__global__ __launch_bounds__(256) void scanA() {
    __shared__ int ss[256];
    int b = blockIdx.x, t = threadIdx.x;
    int base = b * 2048 + t * 8;
    int v[8]; int s = 0;
#pragma unroll
    for (int j = 0; j < 8; j++) {
        int idx = base + j;
        v[j] = (idx < SCAN_NE) ? g_hist[idx] : 0;
        s += v[j];
    }
    ss[t] = s;
    __syncthreads();
    for (int off = 1; off < 256; off <<= 1) {
        int x = (t >= off) ? ss[t - off] : 0;
        __syncthreads();
        ss[t] += x;
        __syncthreads();
    }
    int run = ss[t] - s;
#pragma unroll
    for (int j = 0; j < 8; j++) {
        int idx = base + j;
        run += v[j];
        if (idx < SCAN_NE) g_rowptr[idx] = run;
    }
    if (t == 255) g_bsum[b] = ss[255];
}
__global__ void scanB() {
    if (threadIdx.x == 0) {
        int acc = 0;
        for (int i = 0; i < SCAN_NB; i++) { int v = g_bsum[i]; g_bsum[i] = acc; acc += v; }
    }
}
__global__ void scanC() {
    int i = blockIdx.x * blockDim.x + threadIdx.x;
    if (i < SCAN_NE) {
        int v = g_rowptr[i] + g_bsum[i >> 11];
        g_rowptr[i] = v;
        if (i < N_NODES) g_cur[i] = v;
    }
}
__global__ void fill_csr() {
    int e = blockIdx.x * blockDim.x + threadIdx.x;
    if (e >= N_EDGES) return;
    int s = g_ei[e], d = g_ei[N_EDGES + e];
    int pos = atomicAdd(&g_cur[d], 1);
    g_col[pos] = s;
}
// per-graph node ranges via binary search (batch is sorted)
__global__ void gbounds() {
    int g = blockIdx.x * blockDim.x + threadIdx.x;
    if (g > N_GRAPHS) return;
    int lo = 0, hi = N_NODES;
    while (lo < hi) { int mid = (lo + hi) >> 1; if (g_batch[mid] < g) lo = mid + 1; else hi = mid; }
    g_gstart[g] = lo;
}

// ---------------- layer 0 ----------------
__global__ void scatter11(const float* __restrict__ x, float* __restrict__ agg) {
    int e = blockIdx.x * blockDim.x + threadIdx.x;
    if (e >= N_EDGES) return;
    int s = g_ei[e];
    int d = g_ei[N_EDGES + e];
    const float* xs = x + (size_t)s * INF_DIM;
    float* ag = agg + (size_t)d * INF_DIM;
#pragma unroll
    for (int k = 0; k < INF_DIM; k++) atomicAdd(&ag[k], __ldg(&xs[k]));
}

__global__ __launch_bounds__(256) void l0_mlp(const float* __restrict__ x,
                                              const float* __restrict__ agg,
                                              const float* __restrict__ w1,
                                              const float* __restrict__ b1,
                                              __half* __restrict__ bhi,
                                              __half* __restrict__ blo) {
    __shared__ float sw[INF_DIM * H_DIM];
    __shared__ float sxp[32][INF_DIM];
    int t = threadIdx.x;
    for (int i = t; i < INF_DIM * H_DIM; i += 256) sw[i] = w1[i];
    int nbase = blockIdx.x * 32;
    for (int i = t; i < 32 * INF_DIM; i += 256) {
        int r = i / INF_DIM, k = i % INF_DIM;
        int nn = nbase + r;
        float v = 0.f;
        if (nn < N_NODES) v = x[(size_t)nn * INF_DIM + k] + agg[(size_t)nn * INF_DIM + k];
        sxp[r][k] = v;
    }
    __syncthreads();
    float bias = b1[t];
    for (int r = 0; r < 32; r++) {
        int nn = nbase + r;
        if (nn >= N_NODES) break;
        float s = bias;
#pragma unroll
        for (int k = 0; k < INF_DIM; k++) s = fmaf(sxp[r][k], sw[k * H_DIM + t], s);
        float v = fmaxf(s, 0.f);
        __half h, l;
        split_h(v, h, l);
        bhi[(size_t)nn * H_DIM + t] = h;
        blo[(size_t)nn * H_DIM + t] = l;
    }
}

// ---------------- CSR gather + add + split ----------------
// warp per node: acc = h[n] + sum_{e in CSR[n]} h[col[e]]; write fp16 hi/lo.
__global__ __launch_bounds__(256) void gather_addcvt(const float* __restrict__ h,
                                                     __half* __restrict__ hi,
                                                     __half* __restrict__ lo) {
    int w = (blockIdx.x * blockDim.x + threadIdx.x) >> 5;
    int lane = threadIdx.x & 31;
    if (w >= N_NODES) return;
    int beg = __ldg(&g_rowptr[w]), end = __ldg(&g_rowptr[w + 1]);
    const float* hr = h + (size_t)w * H_DIM;
    float4 a0 = *(const float4*)(hr + lane * 4);
    float4 a1 = *(const float4*)(hr + 128 + lane * 4);
    for (int e = beg; e < end; e++) {
        const float* xr = h + (size_t)__ldg(&g_col[e]) * H_DIM;
        float4 c0 = __ldg((const float4*)(xr + lane * 4));
        float4 c1 = __ldg((const float4*)(xr + 128 + lane * 4));
        a0.x += c0.x; a0.y += c0.y; a0.z += c0.z; a0.w += c0.w;
        a1.x += c1.x; a1.y += c1.y; a1.z += c1.z; a1.w += c1.w;
    }
    __half* dh = hi + (size_t)w * H_DIM;
    __half* dl = lo + (size_t)w * H_DIM;
    float v[8] = {a0.x, a0.y, a0.z, a0.w, a1.x, a1.y, a1.z, a1.w};
#pragma unroll
    for (int half = 0; half < 2; half++) {
        int cb = half * 128 + lane * 4;
        __half h0, h1, h2, h3, l0, l1, l2, l3;
        split_h(v[4 * half + 0], h0, l0);
        split_h(v[4 * half + 1], h1, l1);
        split_h(v[4 * half + 2], h2, l2);
        split_h(v[4 * half + 3], h3, l3);
        __half2 hh0; hh0.x = h0; hh0.y = h1;
        __half2 hh1; hh1.x = h2; hh1.y = h3;
        __half2 ll0; ll0.x = l0; ll0.y = l1;
        __half2 ll1; ll1.x = l2; ll1.y = l3;
        *(__half2*)(dh + cb) = hh0; *(__half2*)(dh + cb + 2) = hh1;
        *(__half2*)(dl + cb) = ll0; *(__half2*)(dl + cb + 2) = ll1;
    }
}

// ---------------- mean pool via sorted-batch segments, output split fp16 ----------------
__global__ __launch_bounds__(256) void pool_gather(const float* __restrict__ h,
                                                   __half* __restrict__ phi,
                                                   __half* __restrict__ plo) {
    int g = (blockIdx.x * blockDim.x + threadIdx.x) >> 5;
    int lane = threadIdx.x & 31;
    if (g >= G_PAD) return;
    float4 a0 = make_float4(0.f, 0.f, 0.f, 0.f);
    float4 a1 = make_float4(0.f, 0.f, 0.f, 0.f);
    float inv = 0.f;
    if (g < N_GRAPHS) {
        int beg = __ldg(&g_gstart[g]), end = __ldg(&g_gstart[g + 1]);
        for (int n = beg; n < end; n++) {
            const float* hr = h + (size_t)n * H_DIM;
            float4 c0 = __ldg((const float4*)(hr + lane * 4));
            float4 c1 = __ldg((const float4*)(hr + 128 + lane * 4));
            a0.x += c0.x; a0.y += c0.y; a0.z += c0.z; a0.w += c0.w;
            a1.x += c1.x; a1.y += c1.y; a1.z += c1.z; a1.w += c1.w;
        }
        int cnt = end - beg;
        inv = 1.f / (float)(cnt > 1 ? cnt : 1);
    }
    float v[8] = {a0.x * inv, a0.y * inv, a0.z * inv, a0.w * inv,
                  a1.x * inv, a1.y * inv, a1.z * inv, a1.w * inv};
    __half* dh = phi + (size_t)g * H_DIM;
    __half* dl = plo + (size_t)g * H_DIM;
#pragma unroll
    for (int half = 0; half < 2; half++) {
        int cb = half * 128 + lane * 4;
        __half h0, h1, h2, h3, l0, l1, l2, l3;
        split_h(v[4 * half + 0], h0, l0);
        split_h(v[4 * half + 1], h1, l1);
        split_h(v[4 * half + 2], h2, l2);
        split_h(v[4 * half + 3], h3, l3);
        __half2 hh0; hh0.x = h0; hh0.y = h1;
        __half2 hh1; hh1.x = h2; hh1.y = h3;
        __half2 ll0; ll0.x = l0; ll0.y = l1;
        __half2 ll1; ll1.x = l2; ll1.y = l3;
        *(__half2*)(dh + cb) = hh0; *(__half2*)(dh + cb + 2) = hh1;
        *(__half2*)(dl + cb) = ll0; *(__half2*)(dl + cb + 2) = ll1;
    }
}

__global__ __launch_bounds__(256) void head_out(const float* __restrict__ hidden,
                                                const float* __restrict__ w2,
                                                const float* __restrict__ b2,
                                                float* __restrict__ out) {
    int g = (blockIdx.x * blockDim.x + threadIdx.x) >> 5;
    int lane = threadIdx.x & 31;
    if (g >= N_GRAPHS) return;
    float s = 0.f;
#pragma unroll
    for (int i = 0; i < 8; i++)
        s = fmaf(hidden[(size_t)g * H_DIM + lane + i * 32], __ldg(&w2[lane + i * 32]), s);
#pragma unroll
    for (int o = 16; o > 0; o >>= 1) s += __shfl_xor_sync(0xFFFFFFFFu, s, o);
    if (lane == 0) out[g] = s + b2[0];
}

// ---------------- host launcher ----------------
extern "C" void kernel_launch(void* const* d_in, const int* in_sizes, int n_in,
                              void* d_out, int out_size) {
    const float* x        = (const float*)d_in[0];
    const void*  ei_raw   = d_in[1];
    const void*  batch_raw= d_in[2];
    const float* gin0_w1  = (const float*)d_in[3];
    const float* gin0_b1  = (const float*)d_in[4];
    const float* gin0_w2  = (const float*)d_in[5];
    const float* gin0_b2  = (const float*)d_in[6];
    const float* gin_w1   = (const float*)d_in[7];
    const float* gin_b1   = (const float*)d_in[8];
    const float* gin_w2   = (const float*)d_in[9];
    const float* gin_b2   = (const float*)d_in[10];
    const float* head_w1  = (const float*)d_in[11];
    const float* head_b1  = (const float*)d_in[12];
    const float* head_w2  = (const float*)d_in[13];
    const float* head_b2  = (const float*)d_in[14];
    float*       out      = (float*)d_out;

    float *pa, *pagg11, *phid;
    __half *pahi, *palo, *pbhi, *pblo, *pwth;
    cudaGetSymbolAddress((void**)&pa,     g_a);
    cudaGetSymbolAddress((void**)&pagg11, g_agg11);
    cudaGetSymbolAddress((void**)&phid,   g_hid);
    cudaGetSymbolAddress((void**)&pahi,   g_ahi);
    cudaGetSymbolAddress((void**)&palo,   g_alo);
    cudaGetSymbolAddress((void**)&pbhi,   g_bhi);
    cudaGetSymbolAddress((void**)&pblo,   g_blo);
    cudaGetSymbolAddress((void**)&pwth,   g_wth);

    cudaFuncSetAttribute(mmagemm, cudaFuncAttributeMaxDynamicSharedMemorySize, NSTAGE * STG_BYTES);

    const dim3 GG(M_PAD / 64, 2);      // 1564 x 2
    const int SMEMB = NSTAGE * STG_BYTES;  // 48KB

    // ---- index dtype detection + conversion ----
    zero_flag<<<1, 1>>>();
    detect32<<<(N_EDGES + 255) / 256, 256>>>((const unsigned int*)ei_raw);
    convert_idx<<<(2 * N_EDGES + 255) / 256, 256>>>(ei_raw, batch_raw);

    cvt_w<<<10 * 256, 256>>>(gin0_w2, gin_w1, gin_w2, head_w1);

    // ---- CSR build + graph bounds ----
    zero_hist<<<(SCAN_NE + 255) / 256, 256>>>();
    hist_dst<<<(N_EDGES + 255) / 256, 256>>>();
    scanA<<<SCAN_NB, 256>>>();
    scanB<<<1, 32>>>();
    scanC<<<(SCAN_NE + 255) / 256, 256>>>();
    fill_csr<<<(N_EDGES + 255) / 256, 256>>>();
    gbounds<<<(N_GRAPHS + 256) / 256, 256>>>();

    // ---- layer 0 (11 -> 256) ----
    {
        int n11 = N_NODES * INF_DIM;
        zero_f<<<(n11 + 255) / 256, 256>>>(pagg11, n11);
        scatter11<<<(N_EDGES + 255) / 256, 256>>>(x, pagg11);
        l0_mlp<<<(N_NODES + 31) / 32, 256>>>(x, pagg11, gin0_w1, gin0_b1, pbhi, pblo);
        mmagemm<<<GG, 256, SMEMB>>>(pbhi, pblo, pwth, gin0_b2,
                                    pa, nullptr, nullptr, 0);
    }

    // ---- layers 1..4 (256 -> 256) ----
    for (int i = 0; i < 4; i++) {
        gather_addcvt<<<(N_NODES * 32 + 255) / 256, 256>>>(pa, pahi, palo);
        mmagemm<<<GG, 256, SMEMB>>>(pahi, palo,
                                    pwth + (size_t)(1 + i) * 65536,
                                    gin_b1 + (size_t)i * H_DIM,
                                    nullptr, pbhi, pblo, 1);
        mmagemm<<<GG, 256, SMEMB>>>(pbhi, pblo,
                                    pwth + (size_t)(5 + i) * 65536,
                                    gin_b2 + (size_t)i * H_DIM,
                                    pa, nullptr, nullptr, 0);
    }

    // ---- global mean pool (segment gather, batch sorted) ----
    pool_gather<<<(G_PAD * 32 + 255) / 256, 256>>>(pa, pahi, palo);

    // ---- head ----
    {
        dim3 HG(G_PAD / 64, 2);
        mmagemm<<<HG, 256, SMEMB>>>(pahi, palo,
                                    pwth + (size_t)9 * 65536,
                                    head_b1, phid, nullptr, nullptr, 2);
    }
    head_out<<<(N_GRAPHS * 32 + 255) / 256, 256>>>(phid, head_w2, head_b2, out);
}

// round 14
// speedup vs baseline: 1.0017x; 1.0017x over previous
#include <cuda_runtime.h>
#include <cuda_fp16.h>
#include <cstdint>

// ---------------- problem constants ----------------
#define N_NODES  100000
#define N_EDGES  400000
#define N_GRAPHS 5000
#define INF_DIM  11
#define H_DIM    256

#define M_PAD    100096   // 782 * 128
#define G_PAD    5120     // 40 * 128
#define SCAN_NE  (N_NODES + 1)
#define SCAN_NB  ((SCAN_NE + 2047) / 2048)   // 49

// ---------------- scratch (static device globals; no allocation) ----------------
__device__ float  g_a  [(size_t)M_PAD * H_DIM];        // fp32 activations (h)
__device__ float  g_agg11[(size_t)N_NODES * INF_DIM];  // layer-0 aggregation
__device__ __half g_ahi[(size_t)M_PAD * H_DIM];        // (h+agg) hi   (also pooled hi)
__device__ __half g_alo[(size_t)M_PAD * H_DIM];        // (h+agg) lo   (also pooled lo)
__device__ __half g_bhi[(size_t)M_PAD * H_DIM];        // hidden hi
__device__ __half g_blo[(size_t)M_PAD * H_DIM];        // hidden lo
__device__ __half g_wth[10 * 65536];                   // W^T fp16 (10 matrices), [n][k]
__device__ float  g_hid [(size_t)G_PAD * H_DIM];
__device__ int    g_ei[2 * N_EDGES];
__device__ int    g_batch[N_NODES];
__device__ int    g_is32;
// CSR by destination
__device__ int    g_hist[SCAN_NE];
__device__ int    g_rowptr[SCAN_NE];
__device__ int    g_cur[N_NODES];
__device__ int    g_bsum[SCAN_NB];
__device__ int    g_col[N_EDGES];
__device__ int    g_gstart[N_GRAPHS + 1];

// ---------------- async-copy helpers (baseline PTX, sm_80+) ----------------
__device__ __forceinline__ uint32_t smem_to_u32(const void* p) {
    uint32_t a;
    asm("{ .reg .u64 t; cvta.to.shared.u64 t, %1; cvt.u32.u64 %0, t; }" : "=r"(a) : "l"(p));
    return a;
}
#define CP_ASYNC16(dst, src) \
    asm volatile("cp.async.cg.shared.global [%0], [%1], 16;" :: "r"(dst), "l"(src))
#define CP_COMMIT()  asm volatile("cp.async.commit_group;" ::: "memory")
#define CP_WAIT0()   asm volatile("cp.async.wait_group 0;" ::: "memory")
#define CP_WAIT1()   asm volatile("cp.async.wait_group 1;" ::: "memory")

// swizzled byte offset: logical tile rows x 32 fp16 (64B), 2 logical rows per 128B
// physical row; (row r, 16B-chunk c in 0..3) -> conflict-free for ldmatrix & cp.async.
__device__ __forceinline__ uint32_t swoff(int r, int c) {
    int pr = r >> 1;
    int pc = (((r & 1) << 2) | c) ^ (pr & 7);
    return (uint32_t)(pr * 128 + pc * 16);
}

__device__ __forceinline__ void ldsm_x4(uint32_t addr, uint32_t* r) {
    asm volatile("ldmatrix.sync.aligned.m8n8.x4.shared.b16 {%0,%1,%2,%3}, [%4];"
                 : "=r"(r[0]), "=r"(r[1]), "=r"(r[2]), "=r"(r[3]) : "r"(addr));
}
__device__ __forceinline__ void mma16816(float* d, const uint32_t* a, const uint32_t* b) {
    asm volatile("mma.sync.aligned.m16n8k16.row.col.f32.f16.f16.f32 "
                 "{%0,%1,%2,%3}, {%4,%5,%6,%7}, {%8,%9}, {%0,%1,%2,%3};"
                 : "+f"(d[0]), "+f"(d[1]), "+f"(d[2]), "+f"(d[3])
                 : "r"(a[0]), "r"(a[1]), "r"(a[2]), "r"(a[3]), "r"(b[0]), "r"(b[1]));
}

// split fp32 -> fp16 hi/lo
__device__ __forceinline__ void split_h(float v, __half& hi, __half& lo) {
    hi = __float2half_rn(v);
    lo = __float2half_rn(v - __half2float(hi));
}

// ================ split-fp16 tensor-core GEMM (R12 config: 2-term, 3-deep) =================
// C[M x 256] = act((Ah + Al)@B^T + bias); A split fp16 (hi/lo), B single fp16; W^T [N][K].
// BM=128, BN=128 (grid.y=2), BK=32, 256 threads = 8 warps, warp tile 32x64.
// 8 stages over K=256; each stage loads Ahi/Alo/B (24KB), does both terms (64 MMA).
// Triple-buffered cp.async (72KB smem/CTA), one __syncthreads per stage, 2 CTAs/SM.
// mode 0: fp32 + relu. mode 1: fp16 hi/lo split + relu. mode 2: fp32, no relu.
#define STG_BYTES 24576          // Ahi 8K | Alo 8K | B 8K
#define NSTAGE 3
__global__ void __launch_bounds__(256, 2) mmagemm(
    const __half* __restrict__ Ahi, const __half* __restrict__ Alo,
    const __half* __restrict__ B,
    const float* __restrict__ bias,
    float* __restrict__ outF,
    __half* __restrict__ outHi, __half* __restrict__ outLo,
    int mode)
{
    extern __shared__ __align__(128) unsigned char sm[];
    const uint32_t sbase = smem_to_u32(sm);

    const int tid = threadIdx.x, wid = tid >> 5, lane = tid & 31;
    const int m0 = blockIdx.x * 128;
    const int n0 = blockIdx.y * 128;
    const int wm = (wid & 3) * 32, wn = (wid >> 2) * 64;

    // copy slots: each 8KB tile = 512 16B-chunks; 2 per thread per tile
    const int cr1 = tid >> 2, cc1 = tid & 3;          // chunk t
    const int cr2 = (tid + 256) >> 2, cc2 = tid & 3;  // chunk t+256
    const uint32_t slot1 = swoff(cr1, cc1);
    const uint32_t slot2 = swoff(cr2, cc2);

    // ldsm row/chunk params
    const int arow0 = wm + ((lane >> 3) & 1) * 8 + (lane & 7);
    const int ach   = lane >> 4;            // 0..1
    const int brow0 = wn + ((lane >> 4) & 1) * 8 + (lane & 7);
    const int bch   = (lane >> 3) & 1;      // 0..1

    float acc[2][8][4];
#pragma unroll
    for (int i = 0; i < 2; i++)
#pragma unroll
        for (int j = 0; j < 8; j++)
#pragma unroll
            for (int k = 0; k < 4; k++) acc[i][j][k] = 0.f;

    auto issue = [&](int st) {
        const int kk = st << 5;
        const uint32_t sa = sbase + (st % NSTAGE) * STG_BYTES;
        CP_ASYNC16(sa +         slot1, Ahi + (size_t)(m0 + cr1) * H_DIM + kk + cc1 * 8);
        CP_ASYNC16(sa +         slot2, Ahi + (size_t)(m0 + cr2) * H_DIM + kk + cc2 * 8);
        CP_ASYNC16(sa +  8192 + slot1, Alo + (size_t)(m0 + cr1) * H_DIM + kk + cc1 * 8);
        CP_ASYNC16(sa +  8192 + slot2, Alo + (size_t)(m0 + cr2) * H_DIM + kk + cc2 * 8);
        CP_ASYNC16(sa + 16384 + slot1, B   + (size_t)(n0 + cr1) * H_DIM + kk + cc1 * 8);
        CP_ASYNC16(sa + 16384 + slot2, B   + (size_t)(n0 + cr2) * H_DIM + kk + cc2 * 8);
        CP_COMMIT();
    };

    issue(0); issue(1);
    for (int st = 0; st < 8; st++) {
        if (st < 7) { CP_WAIT1(); } else { CP_WAIT0(); }
        __syncthreads();
        if (st + 2 < 8) issue(st + 2);   // two stages of cp.async slack

        const uint32_t sa = sbase + (st % NSTAGE) * STG_BYTES;
#pragma unroll
        for (int chunk = 0; chunk < 2; chunk++) {
            const int c0 = chunk * 2;
            uint32_t ah[2][4], al[2][4], b[8][2];
            ldsm_x4(sa +        swoff(arow0,      c0 + ach), ah[0]);
            ldsm_x4(sa +        swoff(arow0 + 16, c0 + ach), ah[1]);
            ldsm_x4(sa + 8192 + swoff(arow0,      c0 + ach), al[0]);
            ldsm_x4(sa + 8192 + swoff(arow0 + 16, c0 + ach), al[1]);
#pragma unroll
            for (int p = 0; p < 4; p++) {
                uint32_t r[4];
                ldsm_x4(sa + 16384 + swoff(brow0 + p * 16, c0 + bch), r);
                b[2 * p][0] = r[0]; b[2 * p][1] = r[1];
                b[2 * p + 1][0] = r[2]; b[2 * p + 1][1] = r[3];
            }
            // term 1: Ah*B
#pragma unroll
            for (int nt = 0; nt < 8; nt++) {
                mma16816(acc[0][nt], ah[0], b[nt]);
                mma16816(acc[1][nt], ah[1], b[nt]);
            }
            // term 2: Al*B
#pragma unroll
            for (int nt = 0; nt < 8; nt++) {
                mma16816(acc[0][nt], al[0], b[nt]);
                mma16816(acc[1][nt], al[1], b[nt]);
            }
        }
    }

    // -------- epilogue --------
#pragma unroll
    for (int mt = 0; mt < 2; mt++) {
#pragma unroll
        for (int nt = 0; nt < 8; nt++) {
            const int ncol = n0 + wn + nt * 8 + (lane & 3) * 2;
            const float b0 = __ldg(&bias[ncol]), b1 = __ldg(&bias[ncol + 1]);
#pragma unroll
            for (int half = 0; half < 2; half++) {
                const int mrow = m0 + wm + mt * 16 + (lane >> 2) + half * 8;
                float v0 = acc[mt][nt][2 * half + 0] + b0;
                float v1 = acc[mt][nt][2 * half + 1] + b1;
                if (mode != 2) { v0 = fmaxf(v0, 0.f); v1 = fmaxf(v1, 0.f); }
                if (mode != 1) {
                    *(float2*)(outF + (size_t)mrow * H_DIM + ncol) = make_float2(v0, v1);
                } else {
                    __half h0, l0v, h1, l1v;
                    split_h(v0, h0, l0v);
                    split_h(v1, h1, l1v);
                    __half2 hh; hh.x = h0; hh.y = h1;
                    __half2 ll; ll.x = l0v; ll.y = l1v;
                    *(__half2*)(outHi + (size_t)mrow * H_DIM + ncol) = hh;
                    *(__half2*)(outLo + (size_t)mrow * H_DIM + ncol) = ll;
                }
            }
        }
    }
}

// ---------------- small utility kernels ----------------
__global__ void zero_f(float* __restrict__ p, int n) {
    int i = blockIdx.x * blockDim.x + threadIdx.x;
    if (i < n) p[i] = 0.f;
}
__global__ void zero_flag() { g_is32 = 0; }

__global__ void detect32(const unsigned int* __restrict__ w) {
    int i = blockIdx.x * blockDim.x + threadIdx.x;
    int idx = 2 * i + 1;
    if (idx < 2 * N_EDGES) { if (w[idx] != 0u) g_is32 = 1; }
}
__global__ void convert_idx(const void* __restrict__ ei_raw, const void* __restrict__ batch_raw) {
    int is32 = g_is32;
    int i = blockIdx.x * blockDim.x + threadIdx.x;
    if (i < 2 * N_EDGES)
        g_ei[i] = is32 ? ((const int*)ei_raw)[i] : (int)((const long long*)ei_raw)[i];
    if (i < N_NODES)
        g_batch[i] = is32 ? ((const int*)batch_raw)[i] : (int)((const long long*)batch_raw)[i];
}

// transpose + convert 10 weight matrices to fp16: wt[mat][n*256+k] = fp16(W[k][n])
__global__ void cvt_w(const float* __restrict__ w0,
                      const float* __restrict__ w1s,
                      const float* __restrict__ w2s,
                      const float* __restrict__ hw1) {
    int b = blockIdx.x;            // 10 * 256 blocks
    int mat = b >> 8, k = b & 255, n = threadIdx.x;
    const float* src = (mat == 0) ? w0
                     : (mat <= 4) ? (w1s + (size_t)(mat - 1) * 65536)
                     : (mat <= 8) ? (w2s + (size_t)(mat - 5) * 65536)
                                  : hw1;
    g_wth[(size_t)mat * 65536 + n * 256 + k] = __float2half_rn(src[k * 256 + n]);
}

// ---------------- CSR build (dst-sorted adjacency) ----------------
__global__ void zero_hist() {
    int i = blockIdx.x * blockDim.x + threadIdx.x;
    if (i < SCAN_NE) g_hist[i] = 0;
}
__global__ void hist_dst() {
    int e = blockIdx.x * blockDim.x + threadIdx.x;
    if (e < N_EDGES) atomicAdd(&g_hist[g_ei[N_EDGES + e] + 1], 1);
}
__global__ __launch_bounds__(256) void scanA() {
    __shared__ int ss[256];
    int b = blockIdx.x, t = threadIdx.x;
    int base = b * 2048 + t * 8;
    int v[8]; int s = 0;
#pragma unroll
    for (int j = 0; j < 8; j++) {
        int idx = base + j;
        v[j] = (idx < SCAN_NE) ? g_hist[idx] : 0;
        s += v[j];
    }
    ss[t] = s;
    __syncthreads();
    for (int off = 1; off < 256; off <<= 1) {
        int x = (t >= off) ? ss[t - off] : 0;
        __syncthreads();
        ss[t] += x;
        __syncthreads();
    }
    int run = ss[t] - s;
#pragma unroll
    for (int j = 0; j < 8; j++) {
        int idx = base + j;
        run += v[j];
        if (idx < SCAN_NE) g_rowptr[idx] = run;
    }
    if (t == 255) g_bsum[b] = ss[255];
}
__global__ void scanB() {
    if (threadIdx.x == 0) {
        int acc = 0;
        for (int i = 0; i < SCAN_NB; i++) { int v = g_bsum[i]; g_bsum[i] = acc; acc += v; }
    }
}
__global__ void scanC() {
    int i = blockIdx.x * blockDim.x + threadIdx.x;
    if (i < SCAN_NE) {
        int v = g_rowptr[i] + g_bsum[i >> 11];
        g_rowptr[i] = v;
        if (i < N_NODES) g_cur[i] = v;
    }
}
__global__ void fill_csr() {
    int e = blockIdx.x * blockDim.x + threadIdx.x;
    if (e >= N_EDGES) return;
    int s = g_ei[e], d = g_ei[N_EDGES + e];
    int pos = atomicAdd(&g_cur[d], 1);
    g_col[pos] = s;
}
// per-graph node ranges via binary search (batch is sorted)
__global__ void gbounds() {
    int g = blockIdx.x * blockDim.x + threadIdx.x;
    if (g > N_GRAPHS) return;
    int lo = 0, hi = N_NODES;
    while (lo < hi) { int mid = (lo + hi) >> 1; if (g_batch[mid] < g) lo = mid + 1; else hi = mid; }
    g_gstart[g] = lo;
}

// ---------------- layer 0 ----------------
__global__ void scatter11(const float* __restrict__ x, float* __restrict__ agg) {
    int e = blockIdx.x * blockDim.x + threadIdx.x;
    if (e >= N_EDGES) return;
    int s = g_ei[e];
    int d = g_ei[N_EDGES + e];
    const float* xs = x + (size_t)s * INF_DIM;
    float* ag = agg + (size_t)d * INF_DIM;
#pragma unroll
    for (int k = 0; k < INF_DIM; k++) atomicAdd(&ag[k], __ldg(&xs[k]));
}

__global__ __launch_bounds__(256) void l0_mlp(const float* __restrict__ x,
                                              const float* __restrict__ agg,
                                              const float* __restrict__ w1,
                                              const float* __restrict__ b1,
                                              __half* __restrict__ bhi,
                                              __half* __restrict__ blo) {
    __shared__ float sw[INF_DIM * H_DIM];
    __shared__ float sxp[32][INF_DIM];
    int t = threadIdx.x;
    for (int i = t; i < INF_DIM * H_DIM; i += 256) sw[i] = w1[i];
    int nbase = blockIdx.x * 32;
    for (int i = t; i < 32 * INF_DIM; i += 256) {
        int r = i / INF_DIM, k = i % INF_DIM;
        int nn = nbase + r;
        float v = 0.f;
        if (nn < N_NODES) v = x[(size_t)nn * INF_DIM + k] + agg[(size_t)nn * INF_DIM + k];
        sxp[r][k] = v;
    }
    __syncthreads();
    float bias = b1[t];
    for (int r = 0; r < 32; r++) {
        int nn = nbase + r;
        if (nn >= N_NODES) break;
        float s = bias;
#pragma unroll
        for (int k = 0; k < INF_DIM; k++) s = fmaf(sxp[r][k], sw[k * H_DIM + t], s);
        float v = fmaxf(s, 0.f);
        __half h, l;
        split_h(v, h, l);
        bhi[(size_t)nn * H_DIM + t] = h;
        blo[(size_t)nn * H_DIM + t] = l;
    }
}

// ---------------- CSR gather + add + split (2 warps per node) ----------------
// warp pair per node: each warp handles 128 of 256 dims; one float4 per lane.
__global__ __launch_bounds__(256) void gather_addcvt(const float* __restrict__ h,
                                                     __half* __restrict__ hi,
                                                     __half* __restrict__ lo) {
    int gw = (blockIdx.x * blockDim.x + threadIdx.x) >> 5;
    int lane = threadIdx.x & 31;
    int w = gw >> 1;            // node
    int hf = gw & 1;            // half of the row
    if (w >= N_NODES) return;
    int beg = __ldg(&g_rowptr[w]), end = __ldg(&g_rowptr[w + 1]);
    const int off = hf * 128 + lane * 4;
    const float* hr = h + (size_t)w * H_DIM + off;
    float4 a0 = *(const float4*)hr;
    for (int e = beg; e < end; e++) {
        const float* xr = h + (size_t)__ldg(&g_col[e]) * H_DIM + off;
        float4 c0 = __ldg((const float4*)xr);
        a0.x += c0.x; a0.y += c0.y; a0.z += c0.z; a0.w += c0.w;
    }
    __half* dh = hi + (size_t)w * H_DIM + off;
    __half* dl = lo + (size_t)w * H_DIM + off;
    __half h0, h1, h2, h3, l0, l1, l2, l3;
    split_h(a0.x, h0, l0);
    split_h(a0.y, h1, l1);
    split_h(a0.z, h2, l2);
    split_h(a0.w, h3, l3);
    __half2 hh0; hh0.x = h0; hh0.y = h1;
    __half2 hh1; hh1.x = h2; hh1.y = h3;
    __half2 ll0; ll0.x = l0; ll0.y = l1;
    __half2 ll1; ll1.x = l2; ll1.y = l3;
    *(__half2*)(dh) = hh0; *(__half2*)(dh + 2) = hh1;
    *(__half2*)(dl) = ll0; *(__half2*)(dl + 2) = ll1;
}

// ---------------- mean pool via sorted-batch segments (2 warps per graph) ----------------
__global__ __launch_bounds__(256) void pool_gather(const float* __restrict__ h,
                                                   __half* __restrict__ phi,
                                                   __half* __restrict__ plo) {
    int gw = (blockIdx.x * blockDim.x + threadIdx.x) >> 5;
    int lane = threadIdx.x & 31;
    int g = gw >> 1;
    int hf = gw & 1;
    if (g >= G_PAD) return;
    const int off = hf * 128 + lane * 4;
    float4 a0 = make_float4(0.f, 0.f, 0.f, 0.f);
    float inv = 0.f;
    if (g < N_GRAPHS) {
        int beg = __ldg(&g_gstart[g]), end = __ldg(&g_gstart[g + 1]);
        for (int n = beg; n < end; n++) {
            float4 c0 = __ldg((const float4*)(h + (size_t)n * H_DIM + off));
            a0.x += c0.x; a0.y += c0.y; a0.z += c0.z; a0.w += c0.w;
        }
        int cnt = end - beg;
        inv = 1.f / (float)(cnt > 1 ? cnt : 1);
    }
    a0.x *= inv; a0.y *= inv; a0.z *= inv; a0.w *= inv;
    __half* dh = phi + (size_t)g * H_DIM + off;
    __half* dl = plo + (size_t)g * H_DIM + off;
    __half h0, h1, h2, h3, l0, l1, l2, l3;
    split_h(a0.x, h0, l0);
    split_h(a0.y, h1, l1);
    split_h(a0.z, h2, l2);
    split_h(a0.w, h3, l3);
    __half2 hh0; hh0.x = h0; hh0.y = h1;
    __half2 hh1; hh1.x = h2; hh1.y = h3;
    __half2 ll0; ll0.x = l0; ll0.y = l1;
    __half2 ll1; ll1.x = l2; ll1.y = l3;
    *(__half2*)(dh) = hh0; *(__half2*)(dh + 2) = hh1;
    *(__half2*)(dl) = ll0; *(__half2*)(dl + 2) = ll1;
}

__global__ __launch_bounds__(256) void head_out(const float* __restrict__ hidden,
                                                const float* __restrict__ w2,
                                                const float* __restrict__ b2,
                                                float* __restrict__ out) {
    int g = (blockIdx.x * blockDim.x + threadIdx.x) >> 5;
    int lane = threadIdx.x & 31;
    if (g >= N_GRAPHS) return;
    float s = 0.f;
#pragma unroll
    for (int i = 0; i < 8; i++)
        s = fmaf(hidden[(size_t)g * H_DIM + lane + i * 32], __ldg(&w2[lane + i * 32]), s);
#pragma unroll
    for (int o = 16; o > 0; o >>= 1) s += __shfl_xor_sync(0xFFFFFFFFu, s, o);
    if (lane == 0) out[g] = s + b2[0];
}

// ---------------- host launcher ----------------
extern "C" void kernel_launch(void* const* d_in, const int* in_sizes, int n_in,
                              void* d_out, int out_size) {
    const float* x        = (const float*)d_in[0];
    const void*  ei_raw   = d_in[1];
    const void*  batch_raw= d_in[2];
    const float* gin0_w1  = (const float*)d_in[3];
    const float* gin0_b1  = (const float*)d_in[4];
    const float* gin0_w2  = (const float*)d_in[5];
    const float* gin0_b2  = (const float*)d_in[6];
    const float* gin_w1   = (const float*)d_in[7];
    const float* gin_b1   = (const float*)d_in[8];
    const float* gin_w2   = (const float*)d_in[9];
    const float* gin_b2   = (const float*)d_in[10];
    const float* head_w1  = (const float*)d_in[11];
    const float* head_b1  = (const float*)d_in[12];
    const float* head_w2  = (const float*)d_in[13];
    const float* head_b2  = (const float*)d_in[14];
    float*       out      = (float*)d_out;

    float *pa, *pagg11, *phid;
    __half *pahi, *palo, *pbhi, *pblo, *pwth;
    cudaGetSymbolAddress((void**)&pa,     g_a);
    cudaGetSymbolAddress((void**)&pagg11, g_agg11);
    cudaGetSymbolAddress((void**)&phid,   g_hid);
    cudaGetSymbolAddress((void**)&pahi,   g_ahi);
    cudaGetSymbolAddress((void**)&palo,   g_alo);
    cudaGetSymbolAddress((void**)&pbhi,   g_bhi);
    cudaGetSymbolAddress((void**)&pblo,   g_blo);
    cudaGetSymbolAddress((void**)&pwth,   g_wth);

    cudaFuncSetAttribute(mmagemm, cudaFuncAttributeMaxDynamicSharedMemorySize, NSTAGE * STG_BYTES);

    const dim3 GG(M_PAD / 128, 2);     // 782 x 2
    const int SMEMB = NSTAGE * STG_BYTES;  // 72KB

    // ---- index dtype detection + conversion ----
    zero_flag<<<1, 1>>>();
    detect32<<<(N_EDGES + 255) / 256, 256>>>((const unsigned int*)ei_raw);
    convert_idx<<<(2 * N_EDGES + 255) / 256, 256>>>(ei_raw, batch_raw);

    cvt_w<<<10 * 256, 256>>>(gin0_w2, gin_w1, gin_w2, head_w1);

    // ---- CSR build + graph bounds ----
    zero_hist<<<(SCAN_NE + 255) / 256, 256>>>();
    hist_dst<<<(N_EDGES + 255) / 256, 256>>>();
    scanA<<<SCAN_NB, 256>>>();
    scanB<<<1, 32>>>();
    scanC<<<(SCAN_NE + 255) / 256, 256>>>();
    fill_csr<<<(N_EDGES + 255) / 256, 256>>>();
    gbounds<<<(N_GRAPHS + 256) / 256, 256>>>();

    // ---- layer 0 (11 -> 256) ----
    {
        int n11 = N_NODES * INF_DIM;
        zero_f<<<(n11 + 255) / 256, 256>>>(pagg11, n11);
        scatter11<<<(N_EDGES + 255) / 256, 256>>>(x, pagg11);
        l0_mlp<<<(N_NODES + 31) / 32, 256>>>(x, pagg11, gin0_w1, gin0_b1, pbhi, pblo);
        mmagemm<<<GG, 256, SMEMB>>>(pbhi, pblo, pwth, gin0_b2,
                                    pa, nullptr, nullptr, 0);
    }

    // ---- layers 1..4 (256 -> 256) ----
    for (int i = 0; i < 4; i++) {
        gather_addcvt<<<(N_NODES * 64 + 255) / 256, 256>>>(pa, pahi, palo);
        mmagemm<<<GG, 256, SMEMB>>>(pahi, palo,
                                    pwth + (size_t)(1 + i) * 65536,
                                    gin_b1 + (size_t)i * H_DIM,
                                    nullptr, pbhi, pblo, 1);
        mmagemm<<<GG, 256, SMEMB>>>(pbhi, pblo,
                                    pwth + (size_t)(5 + i) * 65536,
                                    gin_b2 + (size_t)i * H_DIM,
                                    pa, nullptr, nullptr, 0);
    }

    // ---- global mean pool (segment gather, batch sorted) ----
    pool_gather<<<(G_PAD * 64 + 255) / 256, 256>>>(pa, pahi, palo);

    // ---- head ----
    {
        dim3 HG(G_PAD / 128, 2);
        mmagemm<<<HG, 256, SMEMB>>>(pahi, palo,
                                    pwth + (size_t)9 * 65536,
                                    head_b1, phid, nullptr, nullptr, 2);
    }
    head_out<<<(N_GRAPHS * 32 + 255) / 256, 256>>>(phid, head_w2, head_b2, out);
}

// round 15
// speedup vs baseline: 1.0397x; 1.0379x over previous
#include <cuda_runtime.h>
#include <cuda_fp16.h>
#include <cstdint>

// ---------------- problem constants ----------------
#define N_NODES  100000
#define N_EDGES  400000
#define N_GRAPHS 5000
#define INF_DIM  11
#define H_DIM    256

#define M_PAD    100096   // 782 * 128
#define G_PAD    5120     // 40 * 128
#define SCAN_NE  (N_NODES + 1)
#define SCAN_NB  ((SCAN_NE + 2047) / 2048)   // 49

// ---------------- scratch (static device globals; no allocation) ----------------
__device__ float  g_a  [(size_t)M_PAD * H_DIM];        // fp32 activations (h)
__device__ float  g_agg11[(size_t)N_NODES * INF_DIM];  // layer-0 aggregation
__device__ __half g_ahi[(size_t)M_PAD * H_DIM];        // (h+agg) hi   (also pooled hi)
__device__ __half g_alo[(size_t)M_PAD * H_DIM];        // (h+agg) lo   (also pooled lo)
__device__ __half g_bhi[(size_t)M_PAD * H_DIM];        // hidden hi
__device__ __half g_blo[(size_t)M_PAD * H_DIM];        // hidden lo
__device__ __half g_wth[10 * 65536];                   // W^T fp16 (10 matrices), [n][k]
__device__ float  g_hid [(size_t)G_PAD * H_DIM];
__device__ int    g_ei[2 * N_EDGES];
__device__ int    g_batch[N_NODES];
__device__ int    g_is32;
// CSR by destination
__device__ int    g_hist[SCAN_NE];
__device__ int    g_rowptr[SCAN_NE];
__device__ int    g_cur[N_NODES];
__device__ int    g_bsum[SCAN_NB];
__device__ int    g_col[N_EDGES];
__device__ int    g_gstart[N_GRAPHS + 1];

// ---------------- async-copy helpers (baseline PTX, sm_80+) ----------------
__device__ __forceinline__ uint32_t smem_to_u32(const void* p) {
    uint32_t a;
    asm("{ .reg .u64 t; cvta.to.shared.u64 t, %1; cvt.u32.u64 %0, t; }" : "=r"(a) : "l"(p));
    return a;
}
#define CP_ASYNC16(dst, src) \
    asm volatile("cp.async.cg.shared.global [%0], [%1], 16;" :: "r"(dst), "l"(src))
#define CP_COMMIT()  asm volatile("cp.async.commit_group;" ::: "memory")
#define CP_WAIT0()   asm volatile("cp.async.wait_group 0;" ::: "memory")
#define CP_WAIT1()   asm volatile("cp.async.wait_group 1;" ::: "memory")

// swizzled byte offset: logical tile rows x 32 fp16 (64B), 2 logical rows per 128B
// physical row; (row r, 16B-chunk c in 0..3) -> conflict-free for ldmatrix & cp.async.
__device__ __forceinline__ uint32_t swoff(int r, int c) {
    int pr = r >> 1;
    int pc = (((r & 1) << 2) | c) ^ (pr & 7);
    return (uint32_t)(pr * 128 + pc * 16);
}

__device__ __forceinline__ void ldsm_x4(uint32_t addr, uint32_t* r) {
    asm volatile("ldmatrix.sync.aligned.m8n8.x4.shared.b16 {%0,%1,%2,%3}, [%4];"
                 : "=r"(r[0]), "=r"(r[1]), "=r"(r[2]), "=r"(r[3]) : "r"(addr));
}
__device__ __forceinline__ void mma16816(float* d, const uint32_t* a, const uint32_t* b) {
    asm volatile("mma.sync.aligned.m16n8k16.row.col.f32.f16.f16.f32 "
                 "{%0,%1,%2,%3}, {%4,%5,%6,%7}, {%8,%9}, {%0,%1,%2,%3};"
                 : "+f"(d[0]), "+f"(d[1]), "+f"(d[2]), "+f"(d[3])
                 : "r"(a[0]), "r"(a[1]), "r"(a[2]), "r"(a[3]), "r"(b[0]), "r"(b[1]));
}

// split fp32 -> fp16 hi/lo
__device__ __forceinline__ void split_h(float v, __half& hi, __half& lo) {
    hi = __float2half_rn(v);
    lo = __float2half_rn(v - __half2float(hi));
}

// ================ split-fp16 tensor-core GEMM (R12 config; grid swapped for A reuse) ========
// C[M x 256] = act((Ah + Al)@B^T + bias); A split fp16 (hi/lo), B single fp16; W^T [N][K].
// BM=128, BN=128 (grid.x=2, grid.y=M/128 -> co-scheduled CTA pairs share the A tile),
// BK=32, 256 threads = 8 warps, warp tile 32x64.
// 8 stages over K=256; each stage loads Ahi/Alo/B (24KB), does both terms (64 MMA).
// Triple-buffered cp.async (72KB smem/CTA), one __syncthreads per stage, 2 CTAs/SM.
// mode 0: fp32 + relu. mode 1: fp16 hi/lo split + relu. mode 2: fp32, no relu.
#define STG_BYTES 24576          // Ahi 8K | Alo 8K | B 8K
#define NSTAGE 3
__global__ void __launch_bounds__(256, 2) mmagemm(
    const __half* __restrict__ Ahi, const __half* __restrict__ Alo,
    const __half* __restrict__ B,
    const float* __restrict__ bias,
    float* __restrict__ outF,
    __half* __restrict__ outHi, __half* __restrict__ outLo,
    int mode)
{
    extern __shared__ __align__(128) unsigned char sm[];
    const uint32_t sbase = smem_to_u32(sm);

    const int tid = threadIdx.x, wid = tid >> 5, lane = tid & 31;
    const int m0 = blockIdx.y * 128;     // swapped: y = M tile (x-adjacent CTAs share A)
    const int n0 = blockIdx.x * 128;     // swapped: x = N tile (2 values)
    const int wm = (wid & 3) * 32, wn = (wid >> 2) * 64;

    // copy slots: each 8KB tile = 512 16B-chunks; 2 per thread per tile
    const int cr1 = tid >> 2, cc1 = tid & 3;          // chunk t
    const int cr2 = (tid + 256) >> 2, cc2 = tid & 3;  // chunk t+256
    const uint32_t slot1 = swoff(cr1, cc1);
    const uint32_t slot2 = swoff(cr2, cc2);

    // ldsm row/chunk params
    const int arow0 = wm + ((lane >> 3) & 1) * 8 + (lane & 7);
    const int ach   = lane >> 4;            // 0..1
    const int brow0 = wn + ((lane >> 4) & 1) * 8 + (lane & 7);
    const int bch   = (lane >> 3) & 1;      // 0..1

    float acc[2][8][4];
#pragma unroll
    for (int i = 0; i < 2; i++)
#pragma unroll
        for (int j = 0; j < 8; j++)
#pragma unroll
            for (int k = 0; k < 4; k++) acc[i][j][k] = 0.f;

    auto issue = [&](int st) {
        const int kk = st << 5;
        const uint32_t sa = sbase + (st % NSTAGE) * STG_BYTES;
        CP_ASYNC16(sa +         slot1, Ahi + (size_t)(m0 + cr1) * H_DIM + kk + cc1 * 8);
        CP_ASYNC16(sa +         slot2, Ahi + (size_t)(m0 + cr2) * H_DIM + kk + cc2 * 8);
        CP_ASYNC16(sa +  8192 + slot1, Alo + (size_t)(m0 + cr1) * H_DIM + kk + cc1 * 8);
        CP_ASYNC16(sa +  8192 + slot2, Alo + (size_t)(m0 + cr2) * H_DIM + kk + cc2 * 8);
        CP_ASYNC16(sa + 16384 + slot1, B   + (size_t)(n0 + cr1) * H_DIM + kk + cc1 * 8);
        CP_ASYNC16(sa + 16384 + slot2, B   + (size_t)(n0 + cr2) * H_DIM + kk + cc2 * 8);
        CP_COMMIT();
    };

    issue(0); issue(1);
    for (int st = 0; st < 8; st++) {
        if (st < 7) { CP_WAIT1(); } else { CP_WAIT0(); }
        __syncthreads();
        if (st + 2 < 8) issue(st + 2);   // two stages of cp.async slack

        const uint32_t sa = sbase + (st % NSTAGE) * STG_BYTES;
#pragma unroll
        for (int chunk = 0; chunk < 2; chunk++) {
            const int c0 = chunk * 2;
            uint32_t ah[2][4], al[2][4], b[8][2];
            ldsm_x4(sa +        swoff(arow0,      c0 + ach), ah[0]);
            ldsm_x4(sa +        swoff(arow0 + 16, c0 + ach), ah[1]);
            ldsm_x4(sa + 8192 + swoff(arow0,      c0 + ach), al[0]);
            ldsm_x4(sa + 8192 + swoff(arow0 + 16, c0 + ach), al[1]);
#pragma unroll
            for (int p = 0; p < 4; p++) {
                uint32_t r[4];
                ldsm_x4(sa + 16384 + swoff(brow0 + p * 16, c0 + bch), r);
                b[2 * p][0] = r[0]; b[2 * p][1] = r[1];
                b[2 * p + 1][0] = r[2]; b[2 * p + 1][1] = r[3];
            }
            // term 1: Ah*B
#pragma unroll
            for (int nt = 0; nt < 8; nt++) {
                mma16816(acc[0][nt], ah[0], b[nt]);
                mma16816(acc[1][nt], ah[1], b[nt]);
            }
            // term 2: Al*B
#pragma unroll
            for (int nt = 0; nt < 8; nt++) {
                mma16816(acc[0][nt], al[0], b[nt]);
                mma16816(acc[1][nt], al[1], b[nt]);
            }
        }
    }

    // -------- epilogue --------
#pragma unroll
    for (int mt = 0; mt < 2; mt++) {
#pragma unroll
        for (int nt = 0; nt < 8; nt++) {
            const int ncol = n0 + wn + nt * 8 + (lane & 3) * 2;
            const float b0 = __ldg(&bias[ncol]), b1 = __ldg(&bias[ncol + 1]);
#pragma unroll
            for (int half = 0; half < 2; half++) {
                const int mrow = m0 + wm + mt * 16 + (lane >> 2) + half * 8;
                float v0 = acc[mt][nt][2 * half + 0] + b0;
                float v1 = acc[mt][nt][2 * half + 1] + b1;
                if (mode != 2) { v0 = fmaxf(v0, 0.f); v1 = fmaxf(v1, 0.f); }
                if (mode != 1) {
                    *(float2*)(outF + (size_t)mrow * H_DIM + ncol) = make_float2(v0, v1);
                } else {
                    __half h0, l0v, h1, l1v;
                    split_h(v0, h0, l0v);
                    split_h(v1, h1, l1v);
                    __half2 hh; hh.x = h0; hh.y = h1;
                    __half2 ll; ll.x = l0v; ll.y = l1v;
                    *(__half2*)(outHi + (size_t)mrow * H_DIM + ncol) = hh;
                    *(__half2*)(outLo + (size_t)mrow * H_DIM + ncol) = ll;
                }
            }
        }
    }
}

// ---------------- small utility kernels ----------------
__global__ void zero_flag() { g_is32 = 0; }

__global__ void detect32(const unsigned int* __restrict__ w) {
    int i = blockIdx.x * blockDim.x + threadIdx.x;
    int idx = 2 * i + 1;
    if (idx < 2 * N_EDGES) { if (w[idx] != 0u) g_is32 = 1; }
}
// convert indices + zero g_hist + zero g_agg11 (folded to save launches)
__global__ void convert_idx(const void* __restrict__ ei_raw, const void* __restrict__ batch_raw) {
    int is32 = g_is32;
    int i = blockIdx.x * blockDim.x + threadIdx.x;
    int nthreads = gridDim.x * blockDim.x;
    if (i < 2 * N_EDGES)
        g_ei[i] = is32 ? ((const int*)ei_raw)[i] : (int)((const long long*)ei_raw)[i];
    if (i < N_NODES)
        g_batch[i] = is32 ? ((const int*)batch_raw)[i] : (int)((const long long*)batch_raw)[i];
    if (i < SCAN_NE) g_hist[i] = 0;
    for (int j = i; j < N_NODES * INF_DIM; j += nthreads) g_agg11[j] = 0.f;
}

// transpose + convert 10 weight matrices to fp16: wt[mat][n*256+k] = fp16(W[k][n])
__global__ void cvt_w(const float* __restrict__ w0,
                      const float* __restrict__ w1s,
                      const float* __restrict__ w2s,
                      const float* __restrict__ hw1) {
    int b = blockIdx.x;            // 10 * 256 blocks
    int mat = b >> 8, k = b & 255, n = threadIdx.x;
    const float* src = (mat == 0) ? w0
                     : (mat <= 4) ? (w1s + (size_t)(mat - 1) * 65536)
                     : (mat <= 8) ? (w2s + (size_t)(mat - 5) * 65536)
                                  : hw1;
    g_wth[(size_t)mat * 65536 + n * 256 + k] = __float2half_rn(src[k * 256 + n]);
}

// ---------------- CSR build (dst-sorted adjacency) ----------------
__global__ void hist_dst() {
    int e = blockIdx.x * blockDim.x + threadIdx.x;
    if (e < N_EDGES) atomicAdd(&g_hist[g_ei[N_EDGES + e] + 1], 1);
}
__global__ __launch_bounds__(256) void scanA() {
    __shared__ int ss[256];
    int b = blockIdx.x, t = threadIdx.x;
    int base = b * 2048 + t * 8;
    int v[8]; int s = 0;
#pragma unroll
    for (int j = 0; j < 8; j++) {
        int idx = base + j;
        v[j] = (idx < SCAN_NE) ? g_hist[idx] : 0;
        s += v[j];
    }
    ss[t] = s;
    __syncthreads();
    for (int off = 1; off < 256; off <<= 1) {
        int x = (t >= off) ? ss[t - off] : 0;
        __syncthreads();
        ss[t] += x;
        __syncthreads();
    }
    int run = ss[t] - s;
#pragma unroll
    for (int j = 0; j < 8; j++) {
        int idx = base + j;
        run += v[j];
        if (idx < SCAN_NE) g_rowptr[idx] = run;
    }
    if (t == 255) g_bsum[b] = ss[255];
}
__global__ void scanB() {
    if (threadIdx.x == 0) {
        int acc = 0;
        for (int i = 0; i < SCAN_NB; i++) { int v = g_bsum[i]; g_bsum[i] = acc; acc += v; }
    }
}
__global__ void scanC() {
    int i = blockIdx.x * blockDim.x + threadIdx.x;
    if (i < SCAN_NE) {
        int v = g_rowptr[i] + g_bsum[i >> 11];
        g_rowptr[i] = v;
        if (i < N_NODES) g_cur[i] = v;
    }
}
__global__ void fill_csr() {
    int e = blockIdx.x * blockDim.x + threadIdx.x;
    if (e >= N_EDGES) return;
    int s = g_ei[e], d = g_ei[N_EDGES + e];
    int pos = atomicAdd(&g_cur[d], 1);
    g_col[pos] = s;
}
// per-graph node ranges via binary search (batch is sorted)
__global__ void gbounds() {
    int g = blockIdx.x * blockDim.x + threadIdx.x;
    if (g > N_GRAPHS) return;
    int lo = 0, hi = N_NODES;
    while (lo < hi) { int mid = (lo + hi) >> 1; if (g_batch[mid] < g) lo = mid + 1; else hi = mid; }
    g_gstart[g] = lo;
}

// ---------------- layer 0 ----------------
__global__ void scatter11(const float* __restrict__ x, float* __restrict__ agg) {
    int e = blockIdx.x * blockDim.x + threadIdx.x;
    if (e >= N_EDGES) return;
    int s = g_ei[e];
    int d = g_ei[N_EDGES + e];
    const float* xs = x + (size_t)s * INF_DIM;
    float* ag = agg + (size_t)d * INF_DIM;
#pragma unroll
    for (int k = 0; k < INF_DIM; k++) atomicAdd(&ag[k], __ldg(&xs[k]));
}

__global__ __launch_bounds__(256) void l0_mlp(const float* __restrict__ x,
                                              const float* __restrict__ agg,
                                              const float* __restrict__ w1,
                                              const float* __restrict__ b1,
                                              __half* __restrict__ bhi,
                                              __half* __restrict__ blo) {
    __shared__ float sw[INF_DIM * H_DIM];
    __shared__ float sxp[32][INF_DIM];
    int t = threadIdx.x;
    for (int i = t; i < INF_DIM * H_DIM; i += 256) sw[i] = w1[i];
    int nbase = blockIdx.x * 32;
    for (int i = t; i < 32 * INF_DIM; i += 256) {
        int r = i / INF_DIM, k = i % INF_DIM;
        int nn = nbase + r;
        float v = 0.f;
        if (nn < N_NODES) v = x[(size_t)nn * INF_DIM + k] + agg[(size_t)nn * INF_DIM + k];
        sxp[r][k] = v;
    }
    __syncthreads();
    float bias = b1[t];
    for (int r = 0; r < 32; r++) {
        int nn = nbase + r;
        if (nn >= N_NODES) break;
        float s = bias;
#pragma unroll
        for (int k = 0; k < INF_DIM; k++) s = fmaf(sxp[r][k], sw[k * H_DIM + t], s);
        float v = fmaxf(s, 0.f);
        __half h, l;
        split_h(v, h, l);
        bhi[(size_t)nn * H_DIM + t] = h;
        blo[(size_t)nn * H_DIM + t] = l;
    }
}

// ---------------- CSR gather + add + split (R12: warp per node) ----------------
__global__ __launch_bounds__(256) void gather_addcvt(const float* __restrict__ h,
                                                     __half* __restrict__ hi,
                                                     __half* __restrict__ lo) {
    int w = (blockIdx.x * blockDim.x + threadIdx.x) >> 5;
    int lane = threadIdx.x & 31;
    if (w >= N_NODES) return;
    int beg = __ldg(&g_rowptr[w]), end = __ldg(&g_rowptr[w + 1]);
    const float* hr = h + (size_t)w * H_DIM;
    float4 a0 = *(const float4*)(hr + lane * 4);
    float4 a1 = *(const float4*)(hr + 128 + lane * 4);
    for (int e = beg; e < end; e++) {
        const float* xr = h + (size_t)__ldg(&g_col[e]) * H_DIM;
        float4 c0 = __ldg((const float4*)(xr + lane * 4));
        float4 c1 = __ldg((const float4*)(xr + 128 + lane * 4));
        a0.x += c0.x; a0.y += c0.y; a0.z += c0.z; a0.w += c0.w;
        a1.x += c1.x; a1.y += c1.y; a1.z += c1.z; a1.w += c1.w;
    }
    __half* dh = hi + (size_t)w * H_DIM;
    __half* dl = lo + (size_t)w * H_DIM;
    float v[8] = {a0.x, a0.y, a0.z, a0.w, a1.x, a1.y, a1.z, a1.w};
#pragma unroll
    for (int half = 0; half < 2; half++) {
        int cb = half * 128 + lane * 4;
        __half h0, h1, h2, h3, l0, l1, l2, l3;
        split_h(v[4 * half + 0], h0, l0);
        split_h(v[4 * half + 1], h1, l1);
        split_h(v[4 * half + 2], h2, l2);
        split_h(v[4 * half + 3], h3, l3);
        __half2 hh0; hh0.x = h0; hh0.y = h1;
        __half2 hh1; hh1.x = h2; hh1.y = h3;
        __half2 ll0; ll0.x = l0; ll0.y = l1;
        __half2 ll1; ll1.x = l2; ll1.y = l3;
        *(__half2*)(dh + cb) = hh0; *(__half2*)(dh + cb + 2) = hh1;
        *(__half2*)(dl + cb) = ll0; *(__half2*)(dl + cb + 2) = ll1;
    }
}

// ---------------- mean pool via sorted-batch segments (R12: warp per graph) ----------------
__global__ __launch_bounds__(256) void pool_gather(const float* __restrict__ h,
                                                   __half* __restrict__ phi,
                                                   __half* __restrict__ plo) {
    int g = (blockIdx.x * blockDim.x + threadIdx.x) >> 5;
    int lane = threadIdx.x & 31;
    if (g >= G_PAD) return;
    float4 a0 = make_float4(0.f, 0.f, 0.f, 0.f);
    float4 a1 = make_float4(0.f, 0.f, 0.f, 0.f);
    float inv = 0.f;
    if (g < N_GRAPHS) {
        int beg = __ldg(&g_gstart[g]), end = __ldg(&g_gstart[g + 1]);
        for (int n = beg; n < end; n++) {
            const float* hr = h + (size_t)n * H_DIM;
            float4 c0 = __ldg((const float4*)(hr + lane * 4));
            float4 c1 = __ldg((const float4*)(hr + 128 + lane * 4));
            a0.x += c0.x; a0.y += c0.y; a0.z += c0.z; a0.w += c0.w;
            a1.x += c1.x; a1.y += c1.y; a1.z += c1.z; a1.w += c1.w;
        }
        int cnt = end - beg;
        inv = 1.f / (float)(cnt > 1 ? cnt : 1);
    }
    float v[8] = {a0.x * inv, a0.y * inv, a0.z * inv, a0.w * inv,
                  a1.x * inv, a1.y * inv, a1.z * inv, a1.w * inv};
    __half* dh = phi + (size_t)g * H_DIM;
    __half* dl = plo + (size_t)g * H_DIM;
#pragma unroll
    for (int half = 0; half < 2; half++) {
        int cb = half * 128 + lane * 4;
        __half h0, h1, h2, h3, l0, l1, l2, l3;
        split_h(v[4 * half + 0], h0, l0);
        split_h(v[4 * half + 1], h1, l1);
        split_h(v[4 * half + 2], h2, l2);
        split_h(v[4 * half + 3], h3, l3);
        __half2 hh0; hh0.x = h0; hh0.y = h1;
        __half2 hh1; hh1.x = h2; hh1.y = h3;
        __half2 ll0; ll0.x = l0; ll0.y = l1;
        __half2 ll1; ll1.x = l2; ll1.y = l3;
        *(__half2*)(dh + cb) = hh0; *(__half2*)(dh + cb + 2) = hh1;
        *(__half2*)(dl + cb) = ll0; *(__half2*)(dl + cb + 2) = ll1;
    }
}

__global__ __launch_bounds__(256) void head_out(const float* __restrict__ hidden,
                                                const float* __restrict__ w2,
                                                const float* __restrict__ b2,
                                                float* __restrict__ out) {
    int g = (blockIdx.x * blockDim.x + threadIdx.x) >> 5;
    int lane = threadIdx.x & 31;
    if (g >= N_GRAPHS) return;
    float s = 0.f;
#pragma unroll
    for (int i = 0; i < 8; i++)
        s = fmaf(hidden[(size_t)g * H_DIM + lane + i * 32], __ldg(&w2[lane + i * 32]), s);
#pragma unroll
    for (int o = 16; o > 0; o >>= 1) s += __shfl_xor_sync(0xFFFFFFFFu, s, o);
    if (lane == 0) out[g] = s + b2[0];
}

// ---------------- host launcher ----------------
extern "C" void kernel_launch(void* const* d_in, const int* in_sizes, int n_in,
                              void* d_out, int out_size) {
    const float* x        = (const float*)d_in[0];
    const void*  ei_raw   = d_in[1];
    const void*  batch_raw= d_in[2];
    const float* gin0_w1  = (const float*)d_in[3];
    const float* gin0_b1  = (const float*)d_in[4];
    const float* gin0_w2  = (const float*)d_in[5];
    const float* gin0_b2  = (const float*)d_in[6];
    const float* gin_w1   = (const float*)d_in[7];
    const float* gin_b1   = (const float*)d_in[8];
    const float* gin_w2   = (const float*)d_in[9];
    const float* gin_b2   = (const float*)d_in[10];
    const float* head_w1  = (const float*)d_in[11];
    const float* head_b1  = (const float*)d_in[12];
    const float* head_w2  = (const float*)d_in[13];
    const float* head_b2  = (const float*)d_in[14];
    float*       out      = (float*)d_out;

    float *pa, *pagg11, *phid;
    __half *pahi, *palo, *pbhi, *pblo, *pwth;
    cudaGetSymbolAddress((void**)&pa,     g_a);
    cudaGetSymbolAddress((void**)&pagg11, g_agg11);
    cudaGetSymbolAddress((void**)&phid,   g_hid);
    cudaGetSymbolAddress((void**)&pahi,   g_ahi);
    cudaGetSymbolAddress((void**)&palo,   g_alo);
    cudaGetSymbolAddress((void**)&pbhi,   g_bhi);
    cudaGetSymbolAddress((void**)&pblo,   g_blo);
    cudaGetSymbolAddress((void**)&pwth,   g_wth);

    cudaFuncSetAttribute(mmagemm, cudaFuncAttributeMaxDynamicSharedMemorySize, NSTAGE * STG_BYTES);

    const dim3 GG(2, M_PAD / 128);     // 2 x 782 (x fastest: CTA pairs share A tile)
    const int SMEMB = NSTAGE * STG_BYTES;  // 72KB

    // ---- index dtype detection + conversion (also zeroes hist/agg11) ----
    zero_flag<<<1, 1>>>();
    detect32<<<(N_EDGES + 255) / 256, 256>>>((const unsigned int*)ei_raw);
    convert_idx<<<(2 * N_EDGES + 255) / 256, 256>>>(ei_raw, batch_raw);

    cvt_w<<<10 * 256, 256>>>(gin0_w2, gin_w1, gin_w2, head_w1);

    // ---- CSR build + graph bounds ----
    hist_dst<<<(N_EDGES + 255) / 256, 256>>>();
    scanA<<<SCAN_NB, 256>>>();
    scanB<<<1, 32>>>();
    scanC<<<(SCAN_NE + 255) / 256, 256>>>();
    fill_csr<<<(N_EDGES + 255) / 256, 256>>>();
    gbounds<<<(N_GRAPHS + 256) / 256, 256>>>();

    // ---- layer 0 (11 -> 256) ----
    {
        scatter11<<<(N_EDGES + 255) / 256, 256>>>(x, pagg11);
        l0_mlp<<<(N_NODES + 31) / 32, 256>>>(x, pagg11, gin0_w1, gin0_b1, pbhi, pblo);
        mmagemm<<<GG, 256, SMEMB>>>(pbhi, pblo, pwth, gin0_b2,
                                    pa, nullptr, nullptr, 0);
    }

    // ---- layers 1..4 (256 -> 256) ----
    for (int i = 0; i < 4; i++) {
        gather_addcvt<<<(N_NODES * 32 + 255) / 256, 256>>>(pa, pahi, palo);
        mmagemm<<<GG, 256, SMEMB>>>(pahi, palo,
                                    pwth + (size_t)(1 + i) * 65536,
                                    gin_b1 + (size_t)i * H_DIM,
                                    nullptr, pbhi, pblo, 1);
        mmagemm<<<GG, 256, SMEMB>>>(pbhi, pblo,
                                    pwth + (size_t)(5 + i) * 65536,
                                    gin_b2 + (size_t)i * H_DIM,
                                    pa, nullptr, nullptr, 0);
    }

    // ---- global mean pool (segment gather, batch sorted) ----
    pool_gather<<<(G_PAD * 32 + 255) / 256, 256>>>(pa, pahi, palo);

    // ---- head ----
    {
        dim3 HG(2, G_PAD / 128);
        mmagemm<<<HG, 256, SMEMB>>>(pahi, palo,
                                    pwth + (size_t)9 * 65536,
                                    head_b1, phid, nullptr, nullptr, 2);
    }
    head_out<<<(N_GRAPHS * 32 + 255) / 256, 256>>>(phid, head_w2, head_b2, out);
}

// round 17
// speedup vs baseline: 1.0512x; 1.0111x over previous
#include <cuda_runtime.h>
#include <cuda_fp16.h>
#include <cstdint>

// ---------------- problem constants ----------------
#define N_NODES  100000
#define N_EDGES  400000
#define N_GRAPHS 5000
#define INF_DIM  11
#define H_DIM    256

#define M_PAD    100096   // 782 * 128
#define G_PAD    5120     // 40 * 128
#define SCAN_NE  (N_NODES + 1)
#define SCAN_NB  ((SCAN_NE + 2047) / 2048)   // 49

// ---------------- scratch (static device globals; no allocation) ----------------
__device__ float  g_a  [(size_t)M_PAD * H_DIM];        // fp32 activations (h)
__device__ float  g_agg11[(size_t)N_NODES * INF_DIM];  // layer-0 aggregation
__device__ __half g_ahi[(size_t)M_PAD * H_DIM];        // (h+agg) hi   (also pooled hi)
__device__ __half g_alo[(size_t)M_PAD * H_DIM];        // (h+agg) lo   (also pooled lo)
__device__ __half g_bhi[(size_t)M_PAD * H_DIM];        // hidden hi
__device__ __half g_blo[(size_t)M_PAD * H_DIM];        // hidden lo
__device__ __half g_wth[10 * 65536];                   // W^T fp16 (10 matrices), [n][k]
__device__ float  g_hid [(size_t)G_PAD * H_DIM];
__device__ int    g_ei[2 * N_EDGES];
__device__ int    g_batch[N_NODES];
__device__ int    g_is32;
// CSR by destination
__device__ int    g_hist[SCAN_NE];
__device__ int    g_rowptr[SCAN_NE];
__device__ int    g_cur[N_NODES];
__device__ int    g_bsum[SCAN_NB];
__device__ int    g_col[N_EDGES];
__device__ int    g_gstart[N_GRAPHS + 1];

// ---------------- async-copy helpers (baseline PTX, sm_80+) ----------------
__device__ __forceinline__ uint32_t smem_to_u32(const void* p) {
    uint32_t a;
    asm("{ .reg .u64 t; cvta.to.shared.u64 t, %1; cvt.u32.u64 %0, t; }" : "=r"(a) : "l"(p));
    return a;
}
#define CP_ASYNC16(dst, src) \
    asm volatile("cp.async.cg.shared.global [%0], [%1], 16;" :: "r"(dst), "l"(src))
#define CP_COMMIT()  asm volatile("cp.async.commit_group;" ::: "memory")
#define CP_WAIT0()   asm volatile("cp.async.wait_group 0;" ::: "memory")
#define CP_WAIT1()   asm volatile("cp.async.wait_group 1;" ::: "memory")

// swizzled byte offset: logical tile rows x 32 fp16 (64B), 2 logical rows per 128B
// physical row; (row r, 16B-chunk c in 0..3) -> conflict-free for ldmatrix & cp.async.
__device__ __forceinline__ uint32_t swoff(int r, int c) {
    int pr = r >> 1;
    int pc = (((r & 1) << 2) | c) ^ (pr & 7);
    return (uint32_t)(pr * 128 + pc * 16);
}

__device__ __forceinline__ void ldsm_x4(uint32_t addr, uint32_t* r) {
    asm volatile("ldmatrix.sync.aligned.m8n8.x4.shared.b16 {%0,%1,%2,%3}, [%4];"
                 : "=r"(r[0]), "=r"(r[1]), "=r"(r[2]), "=r"(r[3]) : "r"(addr));
}
__device__ __forceinline__ void mma16816(float* d, const uint32_t* a, const uint32_t* b) {
    asm volatile("mma.sync.aligned.m16n8k16.row.col.f32.f16.f16.f32 "
                 "{%0,%1,%2,%3}, {%4,%5,%6,%7}, {%8,%9}, {%0,%1,%2,%3};"
                 : "+f"(d[0]), "+f"(d[1]), "+f"(d[2]), "+f"(d[3])
                 : "r"(a[0]), "r"(a[1]), "r"(a[2]), "r"(a[3]), "r"(b[0]), "r"(b[1]));
}

// split fp32 -> fp16 hi/lo
__device__ __forceinline__ void split_h(float v, __half& hi, __half& lo) {
    hi = __float2half_rn(v);
    lo = __float2half_rn(v - __half2float(hi));
}

// ================ split-fp16 tensor-core GEMM (persistent-CTA version) =================
// C[M x 256] = act((Ah + Al)@B^T + bias); A split fp16 (hi/lo), B single fp16; W^T [N][K].
// BM=128, BN=128, BK=32, 256 threads = 8 warps, warp tile 32x64.
// Persistent: grid = one full wave (<=296 CTAs), each CTA loops tiles (tile n0 fastest so
// adjacent tiles share the A tile in L2). Next tile's first 2 cp.async stages are
// prefetched BEFORE the epilogue so stores overlap loads. Triple-buffered smem (72KB).
// mode 0: fp32 + relu. mode 1: fp16 hi/lo split + relu. mode 2: fp32, no relu.
#define STG_BYTES 24576          // Ahi 8K | Alo 8K | B 8K
#define NSTAGE 3
__global__ void __launch_bounds__(256, 2) mmagemm(
    const __half* __restrict__ Ahi, const __half* __restrict__ Alo,
    const __half* __restrict__ B,
    const float* __restrict__ bias,
    float* __restrict__ outF,
    __half* __restrict__ outHi, __half* __restrict__ outLo,
    int mtiles, int mode)
{
    extern __shared__ __align__(128) unsigned char sm[];
    const uint32_t sbase = smem_to_u32(sm);

    const int tid = threadIdx.x, wid = tid >> 5, lane = tid & 31;
    const int wm = (wid & 3) * 32, wn = (wid >> 2) * 64;
    const int ntiles = mtiles * 2;

    // copy slots: each 8KB tile = 512 16B-chunks; 2 per thread per tile
    const int cr1 = tid >> 2, cc1 = tid & 3;          // chunk t
    const int cr2 = (tid + 256) >> 2, cc2 = tid & 3;  // chunk t+256
    const uint32_t slot1 = swoff(cr1, cc1);
    const uint32_t slot2 = swoff(cr2, cc2);

    // ldsm row/chunk params
    const int arow0 = wm + ((lane >> 3) & 1) * 8 + (lane & 7);
    const int ach   = lane >> 4;            // 0..1
    const int brow0 = wn + ((lane >> 4) & 1) * 8 + (lane & 7);
    const int bch   = (lane >> 3) & 1;      // 0..1

    auto issue = [&](int st, int m0, int n0) {
        const int kk = st << 5;
        const uint32_t sa = sbase + (st % NSTAGE) * STG_BYTES;
        CP_ASYNC16(sa +         slot1, Ahi + (size_t)(m0 + cr1) * H_DIM + kk + cc1 * 8);
        CP_ASYNC16(sa +         slot2, Ahi + (size_t)(m0 + cr2) * H_DIM + kk + cc2 * 8);
        CP_ASYNC16(sa +  8192 + slot1, Alo + (size_t)(m0 + cr1) * H_DIM + kk + cc1 * 8);
        CP_ASYNC16(sa +  8192 + slot2, Alo + (size_t)(m0 + cr2) * H_DIM + kk + cc2 * 8);
        CP_ASYNC16(sa + 16384 + slot1, B   + (size_t)(n0 + cr1) * H_DIM + kk + cc1 * 8);
        CP_ASYNC16(sa + 16384 + slot2, B   + (size_t)(n0 + cr2) * H_DIM + kk + cc2 * 8);
        CP_COMMIT();
    };

    int tile = blockIdx.x;
    if (tile >= ntiles) return;

    // prime first tile
    {
        const int m0 = (tile >> 1) * 128, n0 = (tile & 1) * 128;
        issue(0, m0, n0);
        issue(1, m0, n0);
    }

    for (; tile < ntiles; tile += gridDim.x) {
        const int m0 = (tile >> 1) * 128, n0 = (tile & 1) * 128;

        float acc[2][8][4];
#pragma unroll
        for (int i = 0; i < 2; i++)
#pragma unroll
            for (int j = 0; j < 8; j++)
#pragma unroll
                for (int k = 0; k < 4; k++) acc[i][j][k] = 0.f;

        for (int st = 0; st < 8; st++) {
            if (st < 7) { CP_WAIT1(); } else { CP_WAIT0(); }
            __syncthreads();
            if (st + 2 < 8) issue(st + 2, m0, n0);

            const uint32_t sa = sbase + (st % NSTAGE) * STG_BYTES;
#pragma unroll
            for (int chunk = 0; chunk < 2; chunk++) {
                const int c0 = chunk * 2;
                uint32_t ah[2][4], al[2][4], b[8][2];
                ldsm_x4(sa +        swoff(arow0,      c0 + ach), ah[0]);
                ldsm_x4(sa +        swoff(arow0 + 16, c0 + ach), ah[1]);
                ldsm_x4(sa + 8192 + swoff(arow0,      c0 + ach), al[0]);
                ldsm_x4(sa + 8192 + swoff(arow0 + 16, c0 + ach), al[1]);
#pragma unroll
                for (int p = 0; p < 4; p++) {
                    uint32_t r[4];
                    ldsm_x4(sa + 16384 + swoff(brow0 + p * 16, c0 + bch), r);
                    b[2 * p][0] = r[0]; b[2 * p][1] = r[1];
                    b[2 * p + 1][0] = r[2]; b[2 * p + 1][1] = r[3];
                }
#pragma unroll
                for (int nt = 0; nt < 8; nt++) {
                    mma16816(acc[0][nt], ah[0], b[nt]);
                    mma16816(acc[1][nt], ah[1], b[nt]);
                }
#pragma unroll
                for (int nt = 0; nt < 8; nt++) {
                    mma16816(acc[0][nt], al[0], b[nt]);
                    mma16816(acc[1][nt], al[1], b[nt]);
                }
            }
        }

        // all warps done reading smem; prefetch next tile's first 2 stages,
        // then the epilogue stores overlap those loads.
        __syncthreads();
        {
            const int nt2 = tile + gridDim.x;
            if (nt2 < ntiles) {
                const int nm0 = (nt2 >> 1) * 128, nn0 = (nt2 & 1) * 128;
                issue(0, nm0, nn0);
                issue(1, nm0, nn0);
            }
        }

        // -------- epilogue --------
#pragma unroll
        for (int mt = 0; mt < 2; mt++) {
#pragma unroll
            for (int nt = 0; nt < 8; nt++) {
                const int ncol = n0 + wn + nt * 8 + (lane & 3) * 2;
                const float b0 = __ldg(&bias[ncol]), b1 = __ldg(&bias[ncol + 1]);
#pragma unroll
                for (int half = 0; half < 2; half++) {
                    const int mrow = m0 + wm + mt * 16 + (lane >> 2) + half * 8;
                    float v0 = acc[mt][nt][2 * half + 0] + b0;
                    float v1 = acc[mt][nt][2 * half + 1] + b1;
                    if (mode != 2) { v0 = fmaxf(v0, 0.f); v1 = fmaxf(v1, 0.f); }
                    if (mode != 1) {
                        *(float2*)(outF + (size_t)mrow * H_DIM + ncol) = make_float2(v0, v1);
                    } else {
                        __half h0, l0v, h1, l1v;
                        split_h(v0, h0, l0v);
                        split_h(v1, h1, l1v);
                        __half2 hh; hh.x = h0; hh.y = h1;
                        __half2 ll; ll.x = l0v; ll.y = l1v;
                        *(__half2*)(outHi + (size_t)mrow * H_DIM + ncol) = hh;
                        *(__half2*)(outLo + (size_t)mrow * H_DIM + ncol) = ll;
                    }
                }
            }
        }
    }
}

// ---------------- small utility kernels ----------------
__global__ void zero_flag() { g_is32 = 0; }

__global__ void detect32(const unsigned int* __restrict__ w) {
    int i = blockIdx.x * blockDim.x + threadIdx.x;
    int idx = 2 * i + 1;
    if (idx < 2 * N_EDGES) { if (w[idx] != 0u) g_is32 = 1; }
}
// convert indices + zero g_hist + zero g_agg11 (folded to save launches)
__global__ void convert_idx(const void* __restrict__ ei_raw, const void* __restrict__ batch_raw) {
    int is32 = g_is32;
    int i = blockIdx.x * blockDim.x + threadIdx.x;
    int nthreads = gridDim.x * blockDim.x;
    if (i < 2 * N_EDGES)
        g_ei[i] = is32 ? ((const int*)ei_raw)[i] : (int)((const long long*)ei_raw)[i];
    if (i < N_NODES)
        g_batch[i] = is32 ? ((const int*)batch_raw)[i] : (int)((const long long*)batch_raw)[i];
    if (i < SCAN_NE) g_hist[i] = 0;
    for (int j = i; j < N_NODES * INF_DIM; j += nthreads) g_agg11[j] = 0.f;
}

// transpose + convert 10 weight matrices to fp16: wt[mat][n*256+k] = fp16(W[k][n])
__global__ void cvt_w(const float* __restrict__ w0,
                      const float* __restrict__ w1s,
                      const float* __restrict__ w2s,
                      const float* __restrict__ hw1) {
    int b = blockIdx.x;            // 10 * 256 blocks
    int mat = b >> 8, k = b & 255, n = threadIdx.x;
    const float* src = (mat == 0) ? w0
                     : (mat <= 4) ? (w1s + (size_t)(mat - 1) * 65536)
                     : (mat <= 8) ? (w2s + (size_t)(mat - 5) * 65536)
                                  : hw1;
    g_wth[(size_t)mat * 65536 + n * 256 + k] = __float2half_rn(src[k * 256 + n]);
}

// ---------------- CSR build (dst-sorted adjacency) ----------------
__global__ void hist_dst() {
    int e = blockIdx.x * blockDim.x + threadIdx.x;
    if (e < N_EDGES) atomicAdd(&g_hist[g_ei[N_EDGES + e] + 1], 1);
}
__global__ __launch_bounds__(256) void scanA() {
    __shared__ int ss[256];
    int b = blockIdx.x, t = threadIdx.x;
    int base = b * 2048 + t * 8;
    int v[8]; int s = 0;
#pragma unroll
    for (int j = 0; j < 8; j++) {
        int idx = base + j;
        v[j] = (idx < SCAN_NE) ? g_hist[idx] : 0;
        s += v[j];
    }
    ss[t] = s;
    __syncthreads();
    for (int off = 1; off < 256; off <<= 1) {
        int x = (t >= off) ? ss[t - off] : 0;
        __syncthreads();
        ss[t] += x;
        __syncthreads();
    }
    int run = ss[t] - s;
#pragma unroll
    for (int j = 0; j < 8; j++) {
        int idx = base + j;
        run += v[j];
        if (idx < SCAN_NE) g_rowptr[idx] = run;
    }
    if (t == 255) g_bsum[b] = ss[255];
}
__global__ void scanB() {
    if (threadIdx.x == 0) {
        int acc = 0;
        for (int i = 0; i < SCAN_NB; i++) { int v = g_bsum[i]; g_bsum[i] = acc; acc += v; }
    }
}
__global__ void scanC() {
    int i = blockIdx.x * blockDim.x + threadIdx.x;
    if (i < SCAN_NE) {
        int v = g_rowptr[i] + g_bsum[i >> 11];
        g_rowptr[i] = v;
        if (i < N_NODES) g_cur[i] = v;
    }
}
__global__ void fill_csr() {
    int e = blockIdx.x * blockDim.x + threadIdx.x;
    if (e >= N_EDGES) return;
    int s = g_ei[e], d = g_ei[N_EDGES + e];
    int pos = atomicAdd(&g_cur[d], 1);
    g_col[pos] = s;
}
// per-graph node ranges via binary search (batch is sorted)
__global__ void gbounds() {
    int g = blockIdx.x * blockDim.x + threadIdx.x;
    if (g > N_GRAPHS) return;
    int lo = 0, hi = N_NODES;
    while (lo < hi) { int mid = (lo + hi) >> 1; if (g_batch[mid] < g) lo = mid + 1; else hi = mid; }
    g_gstart[g] = lo;
}

// ---------------- layer 0 ----------------
__global__ void scatter11(const float* __restrict__ x, float* __restrict__ agg) {
    int e = blockIdx.x * blockDim.x + threadIdx.x;
    if (e >= N_EDGES) return;
    int s = g_ei[e];
    int d = g_ei[N_EDGES + e];
    const float* xs = x + (size_t)s * INF_DIM;
    float* ag = agg + (size_t)d * INF_DIM;
#pragma unroll
    for (int k = 0; k < INF_DIM; k++) atomicAdd(&ag[k], __ldg(&xs[k]));
}

__global__ __launch_bounds__(256) void l0_mlp(const float* __restrict__ x,
                                              const float* __restrict__ agg,
                                              const float* __restrict__ w1,
                                              const float* __restrict__ b1,
                                              __half* __restrict__ bhi,
                                              __half* __restrict__ blo) {
    __shared__ float sw[INF_DIM * H_DIM];
    __shared__ float sxp[32][INF_DIM];
    int t = threadIdx.x;
    for (int i = t; i < INF_DIM * H_DIM; i += 256) sw[i] = w1[i];
    int nbase = blockIdx.x * 32;
    for (int i = t; i < 32 * INF_DIM; i += 256) {
        int r = i / INF_DIM, k = i % INF_DIM;
        int nn = nbase + r;
        float v = 0.f;
        if (nn < N_NODES) v = x[(size_t)nn * INF_DIM + k] + agg[(size_t)nn * INF_DIM + k];
        sxp[r][k] = v;
    }
    __syncthreads();
    float bias = b1[t];
    for (int r = 0; r < 32; r++) {
        int nn = nbase + r;
        if (nn >= N_NODES) break;
        float s = bias;
#pragma unroll
        for (int k = 0; k < INF_DIM; k++) s = fmaf(sxp[r][k], sw[k * H_DIM + t], s);
        float v = fmaxf(s, 0.f);
        __half h, l;
        split_h(v, h, l);
        bhi[(size_t)nn * H_DIM + t] = h;
        blo[(size_t)nn * H_DIM + t] = l;
    }
}

// ---------------- CSR gather + add + split (warp per node) ----------------
__global__ __launch_bounds__(256) void gather_addcvt(const float* __restrict__ h,
                                                     __half* __restrict__ hi,
                                                     __half* __restrict__ lo) {
    int w = (blockIdx.x * blockDim.x + threadIdx.x) >> 5;
    int lane = threadIdx.x & 31;
    if (w >= N_NODES) return;
    int beg = __ldg(&g_rowptr[w]), end = __ldg(&g_rowptr[w + 1]);
    const float* hr = h + (size_t)w * H_DIM;
    float4 a0 = *(const float4*)(hr + lane * 4);
    float4 a1 = *(const float4*)(hr + 128 + lane * 4);
    for (int e = beg; e < end; e++) {
        const float* xr = h + (size_t)__ldg(&g_col[e]) * H_DIM;
        float4 c0 = __ldg((const float4*)(xr + lane * 4));
        float4 c1 = __ldg((const float4*)(xr + 128 + lane * 4));
        a0.x += c0.x; a0.y += c0.y; a0.z += c0.z; a0.w += c0.w;
        a1.x += c1.x; a1.y += c1.y; a1.z += c1.z; a1.w += c1.w;
    }
    __half* dh = hi + (size_t)w * H_DIM;
    __half* dl = lo + (size_t)w * H_DIM;
    float v[8] = {a0.x, a0.y, a0.z, a0.w, a1.x, a1.y, a1.z, a1.w};
#pragma unroll
    for (int half = 0; half < 2; half++) {
        int cb = half * 128 + lane * 4;
        __half h0, h1, h2, h3, l0, l1, l2, l3;
        split_h(v[4 * half + 0], h0, l0);
        split_h(v[4 * half + 1], h1, l1);
        split_h(v[4 * half + 2], h2, l2);
        split_h(v[4 * half + 3], h3, l3);
        __half2 hh0; hh0.x = h0; hh0.y = h1;
        __half2 hh1; hh1.x = h2; hh1.y = h3;
        __half2 ll0; ll0.x = l0; ll0.y = l1;
        __half2 ll1; ll1.x = l2; ll1.y = l3;
        *(__half2*)(dh + cb) = hh0; *(__half2*)(dh + cb + 2) = hh1;
        *(__half2*)(dl + cb) = ll0; *(__half2*)(dl + cb + 2) = ll1;
    }
}

// ---------------- mean pool via sorted-batch segments (warp per graph) ----------------
__global__ __launch_bounds__(256) void pool_gather(const float* __restrict__ h,
                                                   __half* __restrict__ phi,
                                                   __half* __restrict__ plo) {
    int g = (blockIdx.x * blockDim.x + threadIdx.x) >> 5;
    int lane = threadIdx.x & 31;
    if (g >= G_PAD) return;
    float4 a0 = make_float4(0.f, 0.f, 0.f, 0.f);
    float4 a1 = make_float4(0.f, 0.f, 0.f, 0.f);
    float inv = 0.f;
    if (g < N_GRAPHS) {
        int beg = __ldg(&g_gstart[g]), end = __ldg(&g_gstart[g + 1]);
        for (int n = beg; n < end; n++) {
            const float* hr = h + (size_t)n * H_DIM;
            float4 c0 = __ldg((const float4*)(hr + lane * 4));
            float4 c1 = __ldg((const float4*)(hr + 128 + lane * 4));
            a0.x += c0.x; a0.y += c0.y; a0.z += c0.z; a0.w += c0.w;
            a1.x += c1.x; a1.y += c1.y; a1.z += c1.z; a1.w += c1.w;
        }
        int cnt = end - beg;
        inv = 1.f / (float)(cnt > 1 ? cnt : 1);
    }
    float v[8] = {a0.x * inv, a0.y * inv, a0.z * inv, a0.w * inv,
                  a1.x * inv, a1.y * inv, a1.z * inv, a1.w * inv};
    __half* dh = phi + (size_t)g * H_DIM;
    __half* dl = plo + (size_t)g * H_DIM;
#pragma unroll
    for (int half = 0; half < 2; half++) {
        int cb = half * 128 + lane * 4;
        __half h0, h1, h2, h3, l0, l1, l2, l3;
        split_h(v[4 * half + 0], h0, l0);
        split_h(v[4 * half + 1], h1, l1);
        split_h(v[4 * half + 2], h2, l2);
        split_h(v[4 * half + 3], h3, l3);
        __half2 hh0; hh0.x = h0; hh0.y = h1;
        __half2 hh1; hh1.x = h2; hh1.y = h3;
        __half2 ll0; ll0.x = l0; ll0.y = l1;
        __half2 ll1; ll1.x = l2; ll1.y = l3;
        *(__half2*)(dh + cb) = hh0; *(__half2*)(dh + cb + 2) = hh1;
        *(__half2*)(dl + cb) = ll0; *(__half2*)(dl + cb + 2) = ll1;
    }
}

__global__ __launch_bounds__(256) void head_out(const float* __restrict__ hidden,
                                                const float* __restrict__ w2,
                                                const float* __restrict__ b2,
                                                float* __restrict__ out) {
    int g = (blockIdx.x * blockDim.x + threadIdx.x) >> 5;
    int lane = threadIdx.x & 31;
    if (g >= N_GRAPHS) return;
    float s = 0.f;
#pragma unroll
    for (int i = 0; i < 8; i++)
        s = fmaf(hidden[(size_t)g * H_DIM + lane + i * 32], __ldg(&w2[lane + i * 32]), s);
#pragma unroll
    for (int o = 16; o > 0; o >>= 1) s += __shfl_xor_sync(0xFFFFFFFFu, s, o);
    if (lane == 0) out[g] = s + b2[0];
}

// ---------------- host launcher ----------------
extern "C" void kernel_launch(void* const* d_in, const int* in_sizes, int n_in,
                              void* d_out, int out_size) {
    const float* x        = (const float*)d_in[0];
    const void*  ei_raw   = d_in[1];
    const void*  batch_raw= d_in[2];
    const float* gin0_w1  = (const float*)d_in[3];
    const float* gin0_b1  = (const float*)d_in[4];
    const float* gin0_w2  = (const float*)d_in[5];
    const float* gin0_b2  = (const float*)d_in[6];
    const float* gin_w1   = (const float*)d_in[7];
    const float* gin_b1   = (const float*)d_in[8];
    const float* gin_w2   = (const float*)d_in[9];
    const float* gin_b2   = (const float*)d_in[10];
    const float* head_w1  = (const float*)d_in[11];
    const float* head_b1  = (const float*)d_in[12];
    const float* head_w2  = (const float*)d_in[13];
    const float* head_b2  = (const float*)d_in[14];
    float*       out      = (float*)d_out;

    float *pa, *pagg11, *phid;
    __half *pahi, *palo, *pbhi, *pblo, *pwth;
    cudaGetSymbolAddress((void**)&pa,     g_a);
    cudaGetSymbolAddress((void**)&pagg11, g_agg11);
    cudaGetSymbolAddress((void**)&phid,   g_hid);
    cudaGetSymbolAddress((void**)&pahi,   g_ahi);
    cudaGetSymbolAddress((void**)&palo,   g_alo);
    cudaGetSymbolAddress((void**)&pbhi,   g_bhi);
    cudaGetSymbolAddress((void**)&pblo,   g_blo);
    cudaGetSymbolAddress((void**)&pwth,   g_wth);

    cudaFuncSetAttribute(mmagemm, cudaFuncAttributeMaxDynamicSharedMemorySize, NSTAGE * STG_BYTES);

    const int MT   = M_PAD / 128;      // 782 M tiles
    const int GRID = 296;              // one full wave at 2 CTAs/SM
    const int HT   = G_PAD / 128;      // 40
    const int SMEMB = NSTAGE * STG_BYTES;  // 72KB

    // ---- index dtype detection + conversion (also zeroes hist/agg11) ----
    zero_flag<<<1, 1>>>();
    detect32<<<(N_EDGES + 255) / 256, 256>>>((const unsigned int*)ei_raw);
    convert_idx<<<(2 * N_EDGES + 255) / 256, 256>>>(ei_raw, batch_raw);

    cvt_w<<<10 * 256, 256>>>(gin0_w2, gin_w1, gin_w2, head_w1);

    // ---- CSR build + graph bounds ----
    hist_dst<<<(N_EDGES + 255) / 256, 256>>>();
    scanA<<<SCAN_NB, 256>>>();
    scanB<<<1, 32>>>();
    scanC<<<(SCAN_NE + 255) / 256, 256>>>();
    fill_csr<<<(N_EDGES + 255) / 256, 256>>>();
    gbounds<<<(N_GRAPHS + 256) / 256, 256>>>();

    // ---- layer 0 (11 -> 256) ----
    {
        scatter11<<<(N_EDGES + 255) / 256, 256>>>(x, pagg11);
        l0_mlp<<<(N_NODES + 31) / 32, 256>>>(x, pagg11, gin0_w1, gin0_b1, pbhi, pblo);
        mmagemm<<<GRID, 256, SMEMB>>>(pbhi, pblo, pwth, gin0_b2,
                                      pa, nullptr, nullptr, MT, 0);
    }

    // ---- layers 1..4 (256 -> 256) ----
    for (int i = 0; i < 4; i++) {
        gather_addcvt<<<(N_NODES * 32 + 255) / 256, 256>>>(pa, pahi, palo);
        mmagemm<<<GRID, 256, SMEMB>>>(pahi, palo,
                                      pwth + (size_t)(1 + i) * 65536,
                                      gin_b1 + (size_t)i * H_DIM,
                                      nullptr, pbhi, pblo, MT, 1);
        mmagemm<<<GRID, 256, SMEMB>>>(pbhi, pblo,
                                      pwth + (size_t)(5 + i) * 65536,
                                      gin_b2 + (size_t)i * H_DIM,
                                      pa, nullptr, nullptr, MT, 0);
    }

    // ---- global mean pool (segment gather, batch sorted) ----
    pool_gather<<<(G_PAD * 32 + 255) / 256, 256>>>(pa, pahi, palo);

    // ---- head ----
    mmagemm<<<2 * HT, 256, SMEMB>>>(pahi, palo,
                                    pwth + (size_t)9 * 65536,
                                    head_b1, phid, nullptr, nullptr, HT, 2);
    head_out<<<(N_GRAPHS * 32 + 255) / 256, 256>>>(phid, head_w2, head_b2, out);
}